// round 13
// baseline (speedup 1.0000x reference)
#include <cuda_runtime.h>
#include <cuda_bf16.h>
#include <math.h>
#include <stdint.h>

#define NBATCH 64
#define HALF   512
#define INDIM  64
#define HID    256
#define EMB    128
#define MROWS  (NBATCH*HALF)   // 32768 unique rows
#define LN_EPS 1e-5f
#define NTILES (NBATCH*36)

// weight regions inside g_bt_*
#define WOUT_OFS (3*HID*HID)
#define WIN_OFS  (3*HID*HID + EMB*HID)
#define WT_TOTAL (WIN_OFS + HID*INDIM)

// ---------------- device scratch (allocation is forbidden) ------------------
__device__ __align__(16) __nv_bfloat16 g_bt_hi[WT_TOTAL];
__device__ __align__(16) __nv_bfloat16 g_bt_lo[WT_TOTAL];
__device__ __align__(16) __nv_bfloat16 g_zh[MROWS*EMB];   // z hi
__device__ __align__(16) __nv_bfloat16 g_zl[MROWS*EMB];   // z lo
__device__ float g_sq[MROWS];
__device__ float g_s [MROWS];
__device__ float g_w [MROWS];
__device__ int   g_started;
__device__ int   g_cursor;
__device__ int   g_done[NBATCH];

// ---------------- helpers ----------------------------------------------------
__device__ __forceinline__ uint32_t smem_u32(const void* p){
  uint32_t a;
  asm("{ .reg .u64 t; cvta.to.shared.u64 t, %1; cvt.u32.u64 %0, t; }" : "=r"(a) : "l"(p));
  return a;
}
__device__ __forceinline__ void cp16(uint32_t dst, const void* src){
  asm volatile("cp.async.cg.shared.global [%0], [%1], 16;\n" :: "r"(dst), "l"(src));
}
#define CP_COMMIT() asm volatile("cp.async.commit_group;\n" ::: "memory")
#define CP_WAIT(n)  asm volatile("cp.async.wait_group %0;\n" :: "n"(n) : "memory")

__device__ __forceinline__ void ldsm4(uint32_t (&r)[4], uint32_t addr){
  asm volatile("ldmatrix.sync.aligned.m8n8.x4.shared.b16 {%0,%1,%2,%3}, [%4];\n"
    : "=r"(r[0]),"=r"(r[1]),"=r"(r[2]),"=r"(r[3]) : "r"(addr));
}
__device__ __forceinline__ void mma16816(float (&d)[4], const uint32_t (&a)[4],
                                         uint32_t b0, uint32_t b1){
  asm volatile("mma.sync.aligned.m16n8k16.row.col.f32.bf16.bf16.f32 "
    "{%0,%1,%2,%3}, {%4,%5,%6,%7}, {%8,%9}, {%0,%1,%2,%3};\n"
    : "+f"(d[0]),"+f"(d[1]),"+f"(d[2]),"+f"(d[3])
    : "r"(a[0]),"r"(a[1]),"r"(a[2]),"r"(a[3]), "r"(b0),"r"(b1));
}
// rows of 64B (32 bf16); 16B column-chunk c in 0..3; XOR swizzle
__device__ __forceinline__ uint32_t swz(int r, int c){
  return (uint32_t)(r*64 + ((c ^ ((r>>1)&3))<<4));
}
__device__ __forceinline__ void split_bf16(float x, __nv_bfloat16& h, __nv_bfloat16& l){
  h = __float2bfloat16(x);
  l = __float2bfloat16(x - __bfloat162float(h));
}
__device__ __forceinline__ void split2(float v0, float v1, uint32_t& whi, uint32_t& wlo){
  __nv_bfloat16 h0,l0,h1,l1;
  split_bf16(v0,h0,l0); split_bf16(v1,h1,l1);
  whi = ((uint32_t)__bfloat16_as_ushort(h1)<<16) | (uint32_t)__bfloat16_as_ushort(h0);
  wlo = ((uint32_t)__bfloat16_as_ushort(l1)<<16) | (uint32_t)__bfloat16_as_ushort(l0);
}
__device__ __forceinline__ float bf_lo(uint32_t w){
  return __bfloat162float(__ushort_as_bfloat16((unsigned short)(w & 0xffffu)));
}
__device__ __forceinline__ float bf_hi(uint32_t w){
  return __bfloat162float(__ushort_as_bfloat16((unsigned short)(w >> 16)));
}

// warp tile 32 rows x 64 cols, one k32 chunk, bf16x3 accumulate
__device__ __forceinline__ void warp_mma_chunk(
    float (&acc)[2][8][4],
    uint32_t aH, uint32_t aL, uint32_t bH, uint32_t bL,
    int wm, int wn, int lane)
{
  #pragma unroll
  for (int kk=0; kk<2; kk++){
    uint32_t ah[2][4], al[2][4];
    #pragma unroll
    for (int mi=0; mi<2; mi++){
      int row = wm*32 + mi*16 + (lane & 15);
      int c   = kk*2 + (lane >> 4);
      uint32_t off = swz(row, c);
      ldsm4(ah[mi], aH + off);
      ldsm4(al[mi], aL + off);
    }
    #pragma unroll
    for (int p=0; p<4; p++){
      int n = wn*64 + p*16 + ((lane>>4)<<3) + (lane & 7);
      int c = kk*2 + ((lane>>3)&1);
      uint32_t off = swz(n, c);
      uint32_t bh[4], bl[4];
      ldsm4(bh, bH + off);
      ldsm4(bl, bL + off);
      #pragma unroll
      for (int mi=0; mi<2; mi++){
        #pragma unroll
        for (int h=0; h<2; h++){
          mma16816(acc[mi][p*2+h], ah[mi], bh[2*h], bh[2*h+1]);
          mma16816(acc[mi][p*2+h], ah[mi], bl[2*h], bl[2*h+1]);
          mma16816(acc[mi][p*2+h], al[mi], bh[2*h], bh[2*h+1]);
        }
      }
    }
  }
}

// warp tile 32 rows x 32 cols, one k32 chunk, bf16x3
__device__ __forceinline__ void warp_mma_chunk32(
    float (&acc)[2][4][4],
    uint32_t aH, uint32_t aL, uint32_t bH, uint32_t bL,
    int wm, int wn, int lane)
{
  #pragma unroll
  for (int kk=0; kk<2; kk++){
    uint32_t ah[2][4], al[2][4];
    #pragma unroll
    for (int mi=0; mi<2; mi++){
      int row = wm*32 + mi*16 + (lane & 15);
      int c   = kk*2 + (lane >> 4);
      uint32_t off = swz(row, c);
      ldsm4(ah[mi], aH + off);
      ldsm4(al[mi], aL + off);
    }
    #pragma unroll
    for (int p=0; p<2; p++){
      int n = wn*32 + p*16 + ((lane>>4)<<3) + (lane & 7);
      int c = kk*2 + ((lane>>3)&1);
      uint32_t off = swz(n, c);
      uint32_t bh[4], bl[4];
      ldsm4(bh, bH + off);
      ldsm4(bl, bL + off);
      #pragma unroll
      for (int mi=0; mi<2; mi++){
        #pragma unroll
        for (int h=0; h<2; h++){
          mma16816(acc[mi][p*2+h], ah[mi], bh[2*h], bh[2*h+1]);
          mma16816(acc[mi][p*2+h], ah[mi], bl[2*h], bl[2*h+1]);
          mma16816(acc[mi][p*2+h], al[mi], bh[2*h], bh[2*h+1]);
        }
      }
    }
  }
}

// ---------------------------------------------------------------------------
// gram_tile: one 64x64 pairwise-distance tile, 512 threads (16 warps, 16x16
// warp tiles), bf16x3 dual accumulators. Uses smem [0, 64KB).
// ---------------------------------------------------------------------------
__device__ void gram_tile(char* smem, uint32_t sb, int b, int rt, int ct,
                          int tid, int lane, int wid)
{
  const bool diag = (rt == ct);
  const int bofs = b*HALF;
  const int r0 = bofs + rt*64, c0 = bofs + ct*64;

  #pragma unroll
  for (int u=0; u<2; u++){
    int e = tid + u*512;
    int r = e>>4, t2 = e&15;
    int c = t2>>2, q = t2&3;
    uint32_t off = (uint32_t)(c*4096) + swz(r, q);
    size_t gi = (size_t)(r0+r)*EMB + c*32 + q*8;
    cp16(sb + off,         g_zh + gi);
    cp16(sb + 16384 + off, g_zl + gi);
  }
  if (!diag){
    #pragma unroll
    for (int u=0; u<2; u++){
      int e = tid + u*512;
      int r = e>>4, t2 = e&15;
      int c = t2>>2, q = t2&3;
      uint32_t off = (uint32_t)(c*4096) + swz(r, q);
      size_t gi = (size_t)(c0+r)*EMB + c*32 + q*8;
      cp16(sb + 32768 + off, g_zh + gi);
      cp16(sb + 49152 + off, g_zl + gi);
    }
  }
  CP_COMMIT(); CP_WAIT(0);
  __syncthreads();

  const uint32_t bHb = diag ? sb : (sb + 32768);
  const uint32_t bLb = diag ? (sb + 16384) : (sb + 49152);
  const int wm = wid>>2, wn = wid&3;

  float acc[2][4], acc2[2][4];
  #pragma unroll
  for (int h=0;h<2;h++)
    #pragma unroll
    for (int q=0;q<4;q++){ acc[h][q]=0.f; acc2[h][q]=0.f; }

  #pragma unroll
  for (int c=0;c<4;c++){
    #pragma unroll
    for (int kk=0;kk<2;kk++){
      uint32_t ah[4], al[4];
      {
        int row = wm*16 + (lane & 15);
        int cc  = kk*2 + (lane >> 4);
        uint32_t off = (uint32_t)(c*4096) + swz(row, cc);
        ldsm4(ah, sb + off);
        ldsm4(al, sb + 16384 + off);
      }
      int n  = wn*16 + ((lane>>4)<<3) + (lane & 7);
      int cc = kk*2 + ((lane>>3)&1);
      uint32_t off = (uint32_t)(c*4096) + swz(n, cc);
      uint32_t bh[4], bl[4];
      ldsm4(bh, bHb + off);
      ldsm4(bl, bLb + off);
      #pragma unroll
      for (int h=0; h<2; h++){
        mma16816(acc [h], ah, bh[2*h], bh[2*h+1]);
        mma16816(acc2[h], ah, bl[2*h], bl[2*h+1]);
        mma16816(acc2[h], al, bh[2*h], bh[2*h+1]);
      }
    }
  }

  float sqr[2];
  #pragma unroll
  for (int v=0;v<2;v++)
    sqr[v] = __ldcg(&g_sq[r0 + wm*16 + (lane>>2) + v*8]);

  float rsum[2] = {0.f,0.f};
  float csum[4] = {0.f,0.f,0.f,0.f};
  #pragma unroll
  for (int h=0;h<2;h++){
    int colg = c0 + wn*16 + h*8 + 2*(lane&3);
    float sqc0 = __ldcg(&g_sq[colg]), sqc1 = __ldcg(&g_sq[colg+1]);
    float v0 = acc[h][0]+acc2[h][0];
    float v1 = acc[h][1]+acc2[h][1];
    float v2 = acc[h][2]+acc2[h][2];
    float v3 = acc[h][3]+acc2[h][3];
    float d00 = sqrtf(fmaxf(sqr[0] + sqc0 - 2.f*v0, 1e-12f));
    float d01 = sqrtf(fmaxf(sqr[0] + sqc1 - 2.f*v1, 1e-12f));
    float d10 = sqrtf(fmaxf(sqr[1] + sqc0 - 2.f*v2, 1e-12f));
    float d11 = sqrtf(fmaxf(sqr[1] + sqc1 - 2.f*v3, 1e-12f));
    rsum[0] += d00 + d01;
    rsum[1] += d10 + d11;
    csum[h*2+0] += d00 + d10;
    csum[h*2+1] += d01 + d11;
  }
  #pragma unroll
  for (int v=0;v<2;v++){
    rsum[v] += __shfl_xor_sync(0xffffffffu, rsum[v], 1);
    rsum[v] += __shfl_xor_sync(0xffffffffu, rsum[v], 2);
  }
  if ((lane & 3) == 0){
    #pragma unroll
    for (int v=0;v<2;v++)
      atomicAdd(&g_s[r0 + wm*16 + (lane>>2) + v*8], rsum[v]);
  }
  if (!diag){
    #pragma unroll
    for (int i=0;i<4;i++){
      csum[i] += __shfl_xor_sync(0xffffffffu, csum[i], 4);
      csum[i] += __shfl_xor_sync(0xffffffffu, csum[i], 8);
      csum[i] += __shfl_xor_sync(0xffffffffu, csum[i], 16);
    }
    if ((lane >> 2) == 0){
      #pragma unroll
      for (int h=0;h<2;h++){
        int colg = c0 + wn*16 + h*8 + 2*(lane&3);
        atomicAdd(&g_s[colg],   csum[h*2+0]);
        atomicAdd(&g_s[colg+1], csum[h*2+1]);
      }
    }
  }
}

// ---------------------------------------------------------------------------
// prep: transpose + hi/lo split; zero g_s; reset work-stealing state
// ---------------------------------------------------------------------------
__global__ void __launch_bounds__(256) k_prep(
    const float* __restrict__ Wb, const float* __restrict__ Wout,
    const float* __restrict__ Win)
{
  int i = blockIdx.x*256 + threadIdx.x;
  if (i < MROWS) g_s[i] = 0.f;
  if (i < NBATCH) g_done[i] = 0;
  if (i == 0){ g_started = 0; g_cursor = 0; }
  float v;
  if (i < WOUT_OFS){
    int layer = i >> 16;
    int n  = (i >> 8) & 255;
    int kk = i & 255;
    v = Wb[layer*HID*HID + kk*HID + n];
  } else if (i < WIN_OFS){
    int j = i - WOUT_OFS;
    int n  = j >> 8;
    int kk = j & 255;
    v = Wout[kk*EMB + n];
  } else if (i < WT_TOTAL){
    int j = i - WIN_OFS;
    int n  = j >> 6;
    int kk = j & 63;
    v = Win[kk*HID + n];
  } else return;
  __nv_bfloat16 h, l; split_bf16(v, h, l);
  g_bt_hi[i] = h; g_bt_lo[i] = l;
}

// ---------------------------------------------------------------------------
// k_mega: fused delta -> GEMM_in -> 3x blocks -> out+LN, then work-stealing
// gram tiles (only when all mega CTAs have been scheduled).
// ---------------------------------------------------------------------------
#define HHI  0
#define HLO  65536
#define BST  131072
#define PRM  196608
#define PART 199680
#define IDX  203776
#define MEGA_SMEM 204800

__global__ void __launch_bounds__(512) k_mega(
    const float* __restrict__ H, const int* __restrict__ pairs,
    const float* __restrict__ b_in,
    const float* __restrict__ bb, const float* __restrict__ lng,
    const float* __restrict__ lnb,
    const float* __restrict__ bo, const float* __restrict__ lnf_g,
    const float* __restrict__ lnf_b)
{
  extern __shared__ char smem[];
  const uint32_t sb = smem_u32(smem);
  const int tid = threadIdx.x, lane = tid&31, wid = tid>>5;
  const int wm = wid>>2, wn = wid&3;
  const int row0 = blockIdx.x * 128;
  int*   li   = (int*)(smem + IDX);
  int*   ri   = li + 128;
  float* prm  = (float*)(smem + PRM);
  float* part = (float*)(smem + PART);

  if (tid == 0) atomicAdd(&g_started, 1);
  if (tid < 128){
    li[tid] = pairs[2*(row0+tid)];
    ri[tid] = pairs[2*(row0+tid)+1];
  }
  if (tid < 256) prm[tid] = b_in[tid];
  __syncthreads();

  // ---- delta = |H[li]-H[ri]| into h planes 0,1 (K=64) ----
  #pragma unroll
  for (int u=0; u<2; u++){
    int e = tid + u*512;
    int r = e>>3, g = e&7;
    const float* pl = H + (size_t)li[r]*INDIM + g*8;
    const float* pr = H + (size_t)ri[r]*INDIM + g*8;
    float4 a0 = *(const float4*)pl,     a1 = *(const float4*)(pl+4);
    float4 b0 = *(const float4*)pr,     b1 = *(const float4*)(pr+4);
    float d0=fabsf(a0.x-b0.x), d1=fabsf(a0.y-b0.y), d2=fabsf(a0.z-b0.z), d3=fabsf(a0.w-b0.w);
    float d4=fabsf(a1.x-b1.x), d5=fabsf(a1.y-b1.y), d6=fabsf(a1.z-b1.z), d7=fabsf(a1.w-b1.w);
    uint32_t h0,h1,h2,h3,l0,l1,l2,l3;
    split2(d0,d1,h0,l0); split2(d2,d3,h1,l1);
    split2(d4,d5,h2,l2); split2(d6,d7,h3,l3);
    uint32_t off = (uint32_t)((g>>2)*8192) + swz(r, g&3);
    *(uint4*)(smem + HHI + off) = make_uint4(h0,h1,h2,h3);
    *(uint4*)(smem + HLO + off) = make_uint4(l0,l1,l2,l3);
  }

  auto loadB = [&](const __nv_bfloat16* BH, const __nv_bfloat16* BL,
                   int nrows, int kstride, int c, int s){
    uint32_t base = sb + BST + (uint32_t)s*32768;
    int iters = (nrows*4)/512;
    for (int u=0; u<iters; u++){
      int e = tid + u*512;
      int n = e>>2, q = e&3;
      size_t gi = (size_t)n*kstride + c*32 + q*8;
      uint32_t off = swz(n, q);
      cp16(base + off,         BH + gi);
      cp16(base + 16384 + off, BL + gi);
    }
    CP_COMMIT();
  };

  // ================= layer 0: h = delta @ W_in + b_in =================
  {
    const __nv_bfloat16* BH = g_bt_hi + WIN_OFS;
    const __nv_bfloat16* BL = g_bt_lo + WIN_OFS;
    loadB(BH, BL, 256, INDIM, 0, 0);
    loadB(BH, BL, 256, INDIM, 1, 1);
    float acc[2][8][4];
    #pragma unroll
    for (int mi=0;mi<2;mi++)
      #pragma unroll
      for (int j=0;j<8;j++)
        #pragma unroll
        for (int q=0;q<4;q++) acc[mi][j][q]=0.f;
    CP_WAIT(0);
    __syncthreads();
    warp_mma_chunk(acc, sb+HHI,      sb+HLO,      sb+BST,       sb+BST+16384,       wm, wn, lane);
    warp_mma_chunk(acc, sb+HHI+8192, sb+HLO+8192, sb+BST+32768, sb+BST+32768+16384, wm, wn, lane);
    __syncthreads();

    #pragma unroll
    for (int j=0;j<8;j++){
      int col = wn*64 + j*8 + 2*(lane&3);
      float b0 = prm[col], b1 = prm[col+1];
      int p = wn*2 + (j>>2), qj = j&3;
      #pragma unroll
      for (int mi=0;mi<2;mi++){
        #pragma unroll
        for (int h=0;h<2;h++){
          int rl = wm*32 + mi*16 + (lane>>2) + h*8;
          uint32_t adr = (uint32_t)p*8192 + swz(rl, qj) + 4*(lane&3);
          uint32_t whi, wlo;
          split2(acc[mi][j][h*2]+b0, acc[mi][j][h*2+1]+b1, whi, wlo);
          *(uint32_t*)(smem + HHI + adr) = whi;
          *(uint32_t*)(smem + HLO + adr) = wlo;
        }
      }
    }
    __syncthreads();
  }

  // ================= layers 1..3: h += relu(LN(h @ Wb + bb)) =================
  for (int L=0; L<3; L++){
    const __nv_bfloat16* BH = g_bt_hi + (size_t)L*HID*HID;
    const __nv_bfloat16* BL = g_bt_lo + (size_t)L*HID*HID;
    if (tid < 256){
      prm[tid]     = bb [L*HID+tid];
      prm[256+tid] = lng[L*HID+tid];
      prm[512+tid] = lnb[L*HID+tid];
    }
    loadB(BH, BL, 256, HID, 0, 0);
    loadB(BH, BL, 256, HID, 1, 1);

    float acc[2][8][4];
    #pragma unroll
    for (int mi=0;mi<2;mi++)
      #pragma unroll
      for (int j=0;j<8;j++)
        #pragma unroll
        for (int q=0;q<4;q++) acc[mi][j][q]=0.f;

    for (int c=0;c<8;c++){
      if (c<6) { CP_WAIT(1); } else { CP_WAIT(0); }
      __syncthreads();
      uint32_t bbase = sb + BST + (uint32_t)(c&1)*32768;
      warp_mma_chunk(acc, sb+HHI+(uint32_t)c*8192, sb+HLO+(uint32_t)c*8192,
                     bbase, bbase+16384, wm, wn, lane);
      __syncthreads();
      if (c<6) loadB(BH, BL, 256, HID, c+2, c&1);
    }

    float sum[4]={0.f,0.f,0.f,0.f}, ssq[4]={0.f,0.f,0.f,0.f};
    #pragma unroll
    for (int j=0;j<8;j++){
      int col = wn*64 + j*8 + 2*(lane&3);
      float b0 = prm[col], b1 = prm[col+1];
      #pragma unroll
      for (int mi=0;mi<2;mi++){
        acc[mi][j][0]+=b0; acc[mi][j][1]+=b1; acc[mi][j][2]+=b0; acc[mi][j][3]+=b1;
        sum[mi*2+0] += acc[mi][j][0]+acc[mi][j][1];
        ssq[mi*2+0] += acc[mi][j][0]*acc[mi][j][0]+acc[mi][j][1]*acc[mi][j][1];
        sum[mi*2+1] += acc[mi][j][2]+acc[mi][j][3];
        ssq[mi*2+1] += acc[mi][j][2]*acc[mi][j][2]+acc[mi][j][3]*acc[mi][j][3];
      }
    }
    #pragma unroll
    for (int s=0;s<4;s++){
      sum[s]+=__shfl_xor_sync(0xffffffffu,sum[s],1);
      sum[s]+=__shfl_xor_sync(0xffffffffu,sum[s],2);
      ssq[s]+=__shfl_xor_sync(0xffffffffu,ssq[s],1);
      ssq[s]+=__shfl_xor_sync(0xffffffffu,ssq[s],2);
    }
    if ((lane&3)==0){
      #pragma unroll
      for (int mi=0;mi<2;mi++)
        #pragma unroll
        for (int h=0;h<2;h++){
          int row = wm*32 + mi*16 + (lane>>2) + h*8;
          part[(row*4+wn)*2]   = sum[mi*2+h];
          part[(row*4+wn)*2+1] = ssq[mi*2+h];
        }
    }
    __syncthreads();
    float mu[4], rs[4];
    #pragma unroll
    for (int mi=0;mi<2;mi++)
      #pragma unroll
      for (int h=0;h<2;h++){
        int row = wm*32 + mi*16 + (lane>>2) + h*8;
        float s1 = part[(row*4+0)*2]+part[(row*4+1)*2]+part[(row*4+2)*2]+part[(row*4+3)*2];
        float s2 = part[(row*4+0)*2+1]+part[(row*4+1)*2+1]+part[(row*4+2)*2+1]+part[(row*4+3)*2+1];
        int s = mi*2+h;
        mu[s] = s1*(1.f/256.f);
        float var = s2*(1.f/256.f) - mu[s]*mu[s];
        rs[s] = rsqrtf(fmaxf(var,0.f) + LN_EPS);
      }
    #pragma unroll
    for (int j=0;j<8;j++){
      int col = wn*64 + j*8 + 2*(lane&3);
      float lg0 = prm[256+col], lg1 = prm[256+col+1];
      float lb0 = prm[512+col], lb1 = prm[512+col+1];
      int p = wn*2 + (j>>2), qj = j&3;
      #pragma unroll
      for (int mi=0;mi<2;mi++){
        #pragma unroll
        for (int h=0;h<2;h++){
          int rl = wm*32 + mi*16 + (lane>>2) + h*8;
          int s = mi*2+h;
          uint32_t adr = (uint32_t)p*8192 + swz(rl, qj) + 4*(lane&3);
          uint32_t ohh = *(uint32_t*)(smem + HHI + adr);
          uint32_t oll = *(uint32_t*)(smem + HLO + adr);
          float old0 = bf_lo(ohh) + bf_lo(oll);
          float old1 = bf_hi(ohh) + bf_hi(oll);
          float t0 = fmaxf((acc[mi][j][h*2]  -mu[s])*rs[s]*lg0 + lb0, 0.f);
          float t1 = fmaxf((acc[mi][j][h*2+1]-mu[s])*rs[s]*lg1 + lb1, 0.f);
          uint32_t whi, wlo;
          split2(old0+t0, old1+t1, whi, wlo);
          *(uint32_t*)(smem + HHI + adr) = whi;
          *(uint32_t*)(smem + HLO + adr) = wlo;
        }
      }
    }
    __syncthreads();
  }

  // ================= out layer: z = LN(h @ W_out + b_out), sq =================
  {
    const __nv_bfloat16* BH = g_bt_hi + WOUT_OFS;
    const __nv_bfloat16* BL = g_bt_lo + WOUT_OFS;
    if (tid < 128){
      prm[tid]     = bo[tid];
      prm[256+tid] = lnf_g[tid];
      prm[512+tid] = lnf_b[tid];
    }
    loadB(BH, BL, 128, HID, 0, 0);
    loadB(BH, BL, 128, HID, 1, 1);

    float acc[2][4][4];
    #pragma unroll
    for (int mi=0;mi<2;mi++)
      #pragma unroll
      for (int j=0;j<4;j++)
        #pragma unroll
        for (int q=0;q<4;q++) acc[mi][j][q]=0.f;

    for (int c=0;c<8;c++){
      if (c<6) { CP_WAIT(1); } else { CP_WAIT(0); }
      __syncthreads();
      uint32_t bbase = sb + BST + (uint32_t)(c&1)*32768;
      warp_mma_chunk32(acc, sb+HHI+(uint32_t)c*8192, sb+HLO+(uint32_t)c*8192,
                       bbase, bbase+16384, wm, wn, lane);
      __syncthreads();
      if (c<6) loadB(BH, BL, 128, HID, c+2, c&1);
    }

    float sum[4]={0.f,0.f,0.f,0.f}, ssq[4]={0.f,0.f,0.f,0.f};
    #pragma unroll
    for (int j=0;j<4;j++){
      int col = wn*32 + j*8 + 2*(lane&3);
      float b0 = prm[col], b1 = prm[col+1];
      #pragma unroll
      for (int mi=0;mi<2;mi++){
        acc[mi][j][0]+=b0; acc[mi][j][1]+=b1; acc[mi][j][2]+=b0; acc[mi][j][3]+=b1;
        sum[mi*2+0] += acc[mi][j][0]+acc[mi][j][1];
        ssq[mi*2+0] += acc[mi][j][0]*acc[mi][j][0]+acc[mi][j][1]*acc[mi][j][1];
        sum[mi*2+1] += acc[mi][j][2]+acc[mi][j][3];
        ssq[mi*2+1] += acc[mi][j][2]*acc[mi][j][2]+acc[mi][j][3]*acc[mi][j][3];
      }
    }
    #pragma unroll
    for (int s=0;s<4;s++){
      sum[s]+=__shfl_xor_sync(0xffffffffu,sum[s],1);
      sum[s]+=__shfl_xor_sync(0xffffffffu,sum[s],2);
      ssq[s]+=__shfl_xor_sync(0xffffffffu,ssq[s],1);
      ssq[s]+=__shfl_xor_sync(0xffffffffu,ssq[s],2);
    }
    if ((lane&3)==0){
      #pragma unroll
      for (int mi=0;mi<2;mi++)
        #pragma unroll
        for (int h=0;h<2;h++){
          int row = wm*32 + mi*16 + (lane>>2) + h*8;
          part[(row*4+wn)*2]   = sum[mi*2+h];
          part[(row*4+wn)*2+1] = ssq[mi*2+h];
        }
    }
    __syncthreads();
    float mu[4], rs[4];
    #pragma unroll
    for (int mi=0;mi<2;mi++)
      #pragma unroll
      for (int h=0;h<2;h++){
        int row = wm*32 + mi*16 + (lane>>2) + h*8;
        float s1 = part[(row*4+0)*2]+part[(row*4+1)*2]+part[(row*4+2)*2]+part[(row*4+3)*2];
        float s2 = part[(row*4+0)*2+1]+part[(row*4+1)*2+1]+part[(row*4+2)*2+1]+part[(row*4+3)*2+1];
        int s = mi*2+h;
        mu[s] = s1*(1.f/128.f);
        float var = s2*(1.f/128.f) - mu[s]*mu[s];
        rs[s] = rsqrtf(fmaxf(var,0.f) + LN_EPS);
      }
    float qs[4]={0.f,0.f,0.f,0.f};
    #pragma unroll
    for (int j=0;j<4;j++){
      int col = wn*32 + j*8 + 2*(lane&3);
      float lg0 = prm[256+col], lg1 = prm[256+col+1];
      float lb0 = prm[512+col], lb1 = prm[512+col+1];
      #pragma unroll
      for (int mi=0;mi<2;mi++){
        #pragma unroll
        for (int h=0;h<2;h++){
          int rl = wm*32 + mi*16 + (lane>>2) + h*8;
          int s = mi*2+h;
          float t0 = (acc[mi][j][h*2]  -mu[s])*rs[s]*lg0 + lb0;
          float t1 = (acc[mi][j][h*2+1]-mu[s])*rs[s]*lg1 + lb1;
          qs[s] += t0*t0 + t1*t1;
          uint32_t whi, wlo;
          split2(t0, t1, whi, wlo);
          size_t gi = (size_t)(row0+rl)*EMB + col;
          *(uint32_t*)(g_zh + gi) = whi;
          *(uint32_t*)(g_zl + gi) = wlo;
        }
      }
    }
    __syncthreads();
    #pragma unroll
    for (int s=0;s<4;s++){
      qs[s]+=__shfl_xor_sync(0xffffffffu,qs[s],1);
      qs[s]+=__shfl_xor_sync(0xffffffffu,qs[s],2);
    }
    if ((lane&3)==0){
      #pragma unroll
      for (int mi=0;mi<2;mi++)
        #pragma unroll
        for (int h=0;h<2;h++){
          int row = wm*32 + mi*16 + (lane>>2) + h*8;
          part[row*4+wn] = qs[mi*2+h];
        }
    }
    __syncthreads();
    if (wn==0 && (lane&3)==0){
      #pragma unroll
      for (int mi=0;mi<2;mi++)
        #pragma unroll
        for (int h=0;h<2;h++){
          int row = wm*32 + mi*16 + (lane>>2) + h*8;
          g_sq[row0+row] = part[row*4+0]+part[row*4+1]+part[row*4+2]+part[row*4+3];
        }
    }
  }

  // ================= opportunistic gram work-stealing =================
  __syncthreads();
  __threadfence();
  int* comm = (int*)(smem + IDX);
  if (tid == 0){
    atomicAdd(&g_done[blockIdx.x >> 2], 1);
    comm[0] = *(volatile int*)&g_started;
  }
  __syncthreads();
  // exit while any mega CTA is still unscheduled -> free this SM for it
  if (comm[0] < (int)gridDim.x) return;

  for (;;){
    if (tid == 0) comm[1] = atomicAdd(&g_cursor, 1);
    __syncthreads();
    int t = comm[1];
    if (t >= NTILES) return;
    int b = t / 36;
    if (tid == 0){
      while (*(volatile int*)&g_done[b] < 4) __nanosleep(200);
    }
    __syncthreads();
    int tt = t - b*36, rt = 0;
    while (tt >= 8 - rt){ tt -= 8 - rt; rt++; }
    gram_tile(smem, sb, b, rt, rt + tt, tid, lane, wid);
    __syncthreads();
  }
}

// ---------------------------------------------------------------------------
// k_softmax: per batch softmax over 512 unique scores; write w output,
// normalized weights to g_w, zero the f region of out.
// ---------------------------------------------------------------------------
__global__ void __launch_bounds__(256) k_softmax(
    const int* __restrict__ pairs, float* __restrict__ out)
{
  __shared__ float red[256];
  const int b = blockIdx.x, tid = threadIdx.x;
  const float scale = 1.f/(512.f*0.25f);
  float x0 = g_s[b*HALF + tid      ]*scale;
  float x1 = g_s[b*HALF + 256 + tid]*scale;

  red[tid] = fmaxf(x0,x1);
  __syncthreads();
  for (int o=128;o;o>>=1){ if(tid<o) red[tid]=fmaxf(red[tid],red[tid+o]); __syncthreads(); }
  float mx = red[0];
  __syncthreads();

  float e0 = expf(x0-mx), e1 = expf(x1-mx);
  red[tid] = e0+e1;
  __syncthreads();
  for (int o=128;o;o>>=1){ if(tid<o) red[tid]+=red[tid+o]; __syncthreads(); }
  float inv = 1.f/red[0];

  float w0 = e0*inv, w1 = e1*inv;
  g_w[b*HALF + tid]       = w0;
  g_w[b*HALF + 256 + tid] = w1;

  float* wout = out + NBATCH*EMB;
  {
    int p = b*HALF + tid;
    wout[pairs[2*p]]   = w0*0.5f;
    wout[pairs[2*p+1]] = w0*0.5f;
    p = b*HALF + 256 + tid;
    wout[pairs[2*p]]   = w1*0.5f;
    wout[pairs[2*p+1]] = w1*0.5f;
  }
  if (tid < EMB) out[b*EMB + tid] = 0.f;
}

// ---------------------------------------------------------------------------
// k_fsum: f[b] += sum over a 128-row slice of w[i] * z[i].  grid (4, NBATCH).
// ---------------------------------------------------------------------------
__global__ void __launch_bounds__(256) k_fsum(float* __restrict__ out)
{
  __shared__ float wsh[128];
  __shared__ float red[512];
  const int b = blockIdx.y, tid = threadIdx.x;
  const int base = b*HALF + blockIdx.x*128;
  if (tid < 128) wsh[tid] = g_w[base + tid];
  __syncthreads();

  const int c2 = (tid & 63)*2;   // column pair
  const int p  = tid >> 6;       // 0..3 row sub-slice
  float f0 = 0.f, f1 = 0.f;
  #pragma unroll 4
  for (int r=0; r<32; r++){
    int ii = p*32 + r;
    float w = wsh[ii];
    size_t gi = (size_t)(base + ii)*EMB + c2;
    uint32_t zh = *(const uint32_t*)(g_zh + gi);
    uint32_t zl = *(const uint32_t*)(g_zl + gi);
    f0 = fmaf(w, bf_lo(zh) + bf_lo(zl), f0);
    f1 = fmaf(w, bf_hi(zh) + bf_hi(zl), f1);
  }
  red[tid*2]   = f0;
  red[tid*2+1] = f1;
  __syncthreads();
  if (tid < 64){
    float a0 = red[tid*2]   + red[(tid+64)*2]   + red[(tid+128)*2]   + red[(tid+192)*2];
    float a1 = red[tid*2+1] + red[(tid+64)*2+1] + red[(tid+128)*2+1] + red[(tid+192)*2+1];
    atomicAdd(&out[b*EMB + c2],   a0);
    atomicAdd(&out[b*EMB + c2+1], a1);
  }
}

// ---------------------------------------------------------------------------
extern "C" void kernel_launch(void* const* d_in, const int* in_sizes, int n_in,
                              void* d_out, int out_size)
{
  const float* H     = (const float*)d_in[0];
  const int*   pairs = (const int*)  d_in[2];
  const float* W_in  = (const float*)d_in[3];
  const float* b_in  = (const float*)d_in[4];
  const float* Wb    = (const float*)d_in[5];
  const float* bb    = (const float*)d_in[6];
  const float* lng   = (const float*)d_in[7];
  const float* lnb   = (const float*)d_in[8];
  const float* W_out = (const float*)d_in[9];
  const float* b_out = (const float*)d_in[10];
  const float* lnf_g = (const float*)d_in[11];
  const float* lnf_b = (const float*)d_in[12];
  float* out = (float*)d_out;

  cudaFuncSetAttribute(k_mega, cudaFuncAttributeMaxDynamicSharedMemorySize, MEGA_SMEM);

  k_prep<<<(WT_TOTAL + 255)/256, 256>>>(Wb, W_out, W_in);
  k_mega<<<MROWS/128, 512, MEGA_SMEM>>>(H, pairs, b_in, bb, lng, lnb,
                                        b_out, lnf_g, lnf_b);
  k_softmax<<<NBATCH, 256>>>(pairs, out);
  k_fsum<<<dim3(4, NBATCH), 256>>>(out);
}

// round 14
// speedup vs baseline: 1.2473x; 1.2473x over previous
#include <cuda_runtime.h>
#include <cuda_bf16.h>
#include <math.h>
#include <stdint.h>

#define NBATCH 64
#define HALF   512
#define INDIM  64
#define HID    256
#define EMB    128
#define MROWS  (NBATCH*HALF)   // 32768 unique rows
#define LN_EPS 1e-5f

// weight regions inside g_bt_*
#define WOUT_OFS (3*HID*HID)
#define WIN_OFS  (3*HID*HID + EMB*HID)
#define WT_TOTAL (WIN_OFS + HID*INDIM)

// ---------------- device scratch (allocation is forbidden) ------------------
__device__ __align__(16) __nv_bfloat16 g_bt_hi[WT_TOTAL];
__device__ __align__(16) __nv_bfloat16 g_bt_lo[WT_TOTAL];
__device__ __align__(16) __nv_bfloat16 g_zh[MROWS*EMB];   // z hi
__device__ __align__(16) __nv_bfloat16 g_zl[MROWS*EMB];   // z lo
__device__ float g_sq[MROWS];
__device__ float g_s [MROWS];
__device__ float g_w [MROWS];   // normalized softmax weights (unique rows)

// ---------------- helpers ----------------------------------------------------
__device__ __forceinline__ uint32_t smem_u32(const void* p){
  uint32_t a;
  asm("{ .reg .u64 t; cvta.to.shared.u64 t, %1; cvt.u32.u64 %0, t; }" : "=r"(a) : "l"(p));
  return a;
}
__device__ __forceinline__ void cp16(uint32_t dst, const void* src){
  asm volatile("cp.async.cg.shared.global [%0], [%1], 16;\n" :: "r"(dst), "l"(src));
}
#define CP_COMMIT() asm volatile("cp.async.commit_group;\n" ::: "memory")
#define CP_WAIT(n)  asm volatile("cp.async.wait_group %0;\n" :: "n"(n) : "memory")

__device__ __forceinline__ void ldsm4(uint32_t (&r)[4], uint32_t addr){
  asm volatile("ldmatrix.sync.aligned.m8n8.x4.shared.b16 {%0,%1,%2,%3}, [%4];\n"
    : "=r"(r[0]),"=r"(r[1]),"=r"(r[2]),"=r"(r[3]) : "r"(addr));
}
__device__ __forceinline__ void mma16816(float (&d)[4], const uint32_t (&a)[4],
                                         uint32_t b0, uint32_t b1){
  asm volatile("mma.sync.aligned.m16n8k16.row.col.f32.bf16.bf16.f32 "
    "{%0,%1,%2,%3}, {%4,%5,%6,%7}, {%8,%9}, {%0,%1,%2,%3};\n"
    : "+f"(d[0]),"+f"(d[1]),"+f"(d[2]),"+f"(d[3])
    : "r"(a[0]),"r"(a[1]),"r"(a[2]),"r"(a[3]), "r"(b0),"r"(b1));
}
// rows of 64B (32 bf16); 16B column-chunk c in 0..3; XOR swizzle
__device__ __forceinline__ uint32_t swz(int r, int c){
  return (uint32_t)(r*64 + ((c ^ ((r>>1)&3))<<4));
}
__device__ __forceinline__ void split_bf16(float x, __nv_bfloat16& h, __nv_bfloat16& l){
  h = __float2bfloat16(x);
  l = __float2bfloat16(x - __bfloat162float(h));
}
__device__ __forceinline__ void split2(float v0, float v1, uint32_t& whi, uint32_t& wlo){
  __nv_bfloat16 h0,l0,h1,l1;
  split_bf16(v0,h0,l0); split_bf16(v1,h1,l1);
  whi = ((uint32_t)__bfloat16_as_ushort(h1)<<16) | (uint32_t)__bfloat16_as_ushort(h0);
  wlo = ((uint32_t)__bfloat16_as_ushort(l1)<<16) | (uint32_t)__bfloat16_as_ushort(l0);
}
__device__ __forceinline__ float bf_lo(uint32_t w){
  return __bfloat162float(__ushort_as_bfloat16((unsigned short)(w & 0xffffu)));
}
__device__ __forceinline__ float bf_hi(uint32_t w){
  return __bfloat162float(__ushort_as_bfloat16((unsigned short)(w >> 16)));
}

// warp tile 32 rows x 64 cols, one k32 chunk, bf16x3 accumulate
__device__ __forceinline__ void warp_mma_chunk(
    float (&acc)[2][8][4],
    uint32_t aH, uint32_t aL, uint32_t bH, uint32_t bL,
    int wm, int wn, int lane)
{
  #pragma unroll
  for (int kk=0; kk<2; kk++){
    uint32_t ah[2][4], al[2][4];
    #pragma unroll
    for (int mi=0; mi<2; mi++){
      int row = wm*32 + mi*16 + (lane & 15);
      int c   = kk*2 + (lane >> 4);
      uint32_t off = swz(row, c);
      ldsm4(ah[mi], aH + off);
      ldsm4(al[mi], aL + off);
    }
    #pragma unroll
    for (int p=0; p<4; p++){
      int n = wn*64 + p*16 + ((lane>>4)<<3) + (lane & 7);
      int c = kk*2 + ((lane>>3)&1);
      uint32_t off = swz(n, c);
      uint32_t bh[4], bl[4];
      ldsm4(bh, bH + off);
      ldsm4(bl, bL + off);
      #pragma unroll
      for (int mi=0; mi<2; mi++){
        #pragma unroll
        for (int h=0; h<2; h++){
          mma16816(acc[mi][p*2+h], ah[mi], bh[2*h], bh[2*h+1]);
          mma16816(acc[mi][p*2+h], ah[mi], bl[2*h], bl[2*h+1]);
          mma16816(acc[mi][p*2+h], al[mi], bh[2*h], bh[2*h+1]);
        }
      }
    }
  }
}

// warp tile 32 rows x 32 cols, one k32 chunk, bf16x3
__device__ __forceinline__ void warp_mma_chunk32(
    float (&acc)[2][4][4],
    uint32_t aH, uint32_t aL, uint32_t bH, uint32_t bL,
    int wm, int wn, int lane)
{
  #pragma unroll
  for (int kk=0; kk<2; kk++){
    uint32_t ah[2][4], al[2][4];
    #pragma unroll
    for (int mi=0; mi<2; mi++){
      int row = wm*32 + mi*16 + (lane & 15);
      int c   = kk*2 + (lane >> 4);
      uint32_t off = swz(row, c);
      ldsm4(ah[mi], aH + off);
      ldsm4(al[mi], aL + off);
    }
    #pragma unroll
    for (int p=0; p<2; p++){
      int n = wn*32 + p*16 + ((lane>>4)<<3) + (lane & 7);
      int c = kk*2 + ((lane>>3)&1);
      uint32_t off = swz(n, c);
      uint32_t bh[4], bl[4];
      ldsm4(bh, bH + off);
      ldsm4(bl, bL + off);
      #pragma unroll
      for (int mi=0; mi<2; mi++){
        #pragma unroll
        for (int h=0; h<2; h++){
          mma16816(acc[mi][p*2+h], ah[mi], bh[2*h], bh[2*h+1]);
          mma16816(acc[mi][p*2+h], ah[mi], bl[2*h], bl[2*h+1]);
          mma16816(acc[mi][p*2+h], al[mi], bh[2*h], bh[2*h+1]);
        }
      }
    }
  }
}

// gram bf16x3 with dual accumulators
__device__ __forceinline__ void warp_mma_gram3(
    float (&acc)[2][4][4], float (&acc2)[2][4][4],
    uint32_t aH, uint32_t aL, uint32_t bH, uint32_t bL,
    int wm, int wn, int lane)
{
  #pragma unroll
  for (int kk=0; kk<2; kk++){
    uint32_t ah[2][4], al[2][4];
    #pragma unroll
    for (int mi=0; mi<2; mi++){
      int row = wm*32 + mi*16 + (lane & 15);
      int c   = kk*2 + (lane >> 4);
      uint32_t off = swz(row, c);
      ldsm4(ah[mi], aH + off);
      ldsm4(al[mi], aL + off);
    }
    #pragma unroll
    for (int p=0; p<2; p++){
      int n = wn*32 + p*16 + ((lane>>4)<<3) + (lane & 7);
      int c = kk*2 + ((lane>>3)&1);
      uint32_t off = swz(n, c);
      uint32_t bh[4], bl[4];
      ldsm4(bh, bH + off);
      ldsm4(bl, bL + off);
      #pragma unroll
      for (int mi=0; mi<2; mi++){
        #pragma unroll
        for (int h=0; h<2; h++){
          mma16816(acc [mi][p*2+h], ah[mi], bh[2*h], bh[2*h+1]);
          mma16816(acc2[mi][p*2+h], ah[mi], bl[2*h], bl[2*h+1]);
          mma16816(acc2[mi][p*2+h], al[mi], bh[2*h], bh[2*h+1]);
        }
      }
    }
  }
}

// ---------------------------------------------------------------------------
// prep: transpose + hi/lo split of Wb, W_out, W_in; zero g_s
// ---------------------------------------------------------------------------
__global__ void __launch_bounds__(256) k_prep(
    const float* __restrict__ Wb, const float* __restrict__ Wout,
    const float* __restrict__ Win)
{
  int i = blockIdx.x*256 + threadIdx.x;
  if (i < MROWS) g_s[i] = 0.f;
  float v;
  if (i < WOUT_OFS){
    int layer = i >> 16;
    int n  = (i >> 8) & 255;
    int kk = i & 255;
    v = Wb[layer*HID*HID + kk*HID + n];
  } else if (i < WIN_OFS){
    int j = i - WOUT_OFS;
    int n  = j >> 8;
    int kk = j & 255;
    v = Wout[kk*EMB + n];
  } else if (i < WT_TOTAL){
    int j = i - WIN_OFS;
    int n  = j >> 6;
    int kk = j & 63;
    v = Win[kk*HID + n];
  } else return;
  __nv_bfloat16 h, l; split_bf16(v, h, l);
  g_bt_hi[i] = h; g_bt_lo[i] = l;
}

// ---------------------------------------------------------------------------
// k_mega (proven config): fused delta -> GEMM_in -> 3x blocks -> out+LN
// M=128 rows/CTA, 512 threads (16 warps, 4M x 4N of 32x64 tiles), 2-stage B.
// ---------------------------------------------------------------------------
#define HHI  0
#define HLO  65536
#define BST  131072
#define PRM  196608
#define PART 199680
#define IDX  203776
#define MEGA_SMEM 204800

__global__ void __launch_bounds__(512) k_mega(
    const float* __restrict__ H, const int* __restrict__ pairs,
    const float* __restrict__ b_in,
    const float* __restrict__ bb, const float* __restrict__ lng,
    const float* __restrict__ lnb,
    const float* __restrict__ bo, const float* __restrict__ lnf_g,
    const float* __restrict__ lnf_b)
{
  extern __shared__ char smem[];
  const uint32_t sb = smem_u32(smem);
  const int tid = threadIdx.x, lane = tid&31, wid = tid>>5;
  const int wm = wid>>2, wn = wid&3;
  const int row0 = blockIdx.x * 128;
  int*   li   = (int*)(smem + IDX);
  int*   ri   = li + 128;
  float* prm  = (float*)(smem + PRM);
  float* part = (float*)(smem + PART);

  if (tid < 128){
    li[tid] = pairs[2*(row0+tid)];
    ri[tid] = pairs[2*(row0+tid)+1];
  }
  if (tid < 256) prm[tid] = b_in[tid];
  __syncthreads();

  // ---- delta = |H[li]-H[ri]| into h planes 0,1 (K=64) ----
  #pragma unroll
  for (int u=0; u<2; u++){
    int e = tid + u*512;
    int r = e>>3, g = e&7;
    const float* pl = H + (size_t)li[r]*INDIM + g*8;
    const float* pr = H + (size_t)ri[r]*INDIM + g*8;
    float4 a0 = *(const float4*)pl,     a1 = *(const float4*)(pl+4);
    float4 b0 = *(const float4*)pr,     b1 = *(const float4*)(pr+4);
    float d0=fabsf(a0.x-b0.x), d1=fabsf(a0.y-b0.y), d2=fabsf(a0.z-b0.z), d3=fabsf(a0.w-b0.w);
    float d4=fabsf(a1.x-b1.x), d5=fabsf(a1.y-b1.y), d6=fabsf(a1.z-b1.z), d7=fabsf(a1.w-b1.w);
    uint32_t h0,h1,h2,h3,l0,l1,l2,l3;
    split2(d0,d1,h0,l0); split2(d2,d3,h1,l1);
    split2(d4,d5,h2,l2); split2(d6,d7,h3,l3);
    uint32_t off = (uint32_t)((g>>2)*8192) + swz(r, g&3);
    *(uint4*)(smem + HHI + off) = make_uint4(h0,h1,h2,h3);
    *(uint4*)(smem + HLO + off) = make_uint4(l0,l1,l2,l3);
  }

  auto loadB = [&](const __nv_bfloat16* BH, const __nv_bfloat16* BL,
                   int nrows, int kstride, int c, int s){
    uint32_t base = sb + BST + (uint32_t)s*32768;
    int iters = (nrows*4)/512;
    for (int u=0; u<iters; u++){
      int e = tid + u*512;
      int n = e>>2, q = e&3;
      size_t gi = (size_t)n*kstride + c*32 + q*8;
      uint32_t off = swz(n, q);
      cp16(base + off,         BH + gi);
      cp16(base + 16384 + off, BL + gi);
    }
    CP_COMMIT();
  };

  // ================= layer 0: h = delta @ W_in + b_in =================
  {
    const __nv_bfloat16* BH = g_bt_hi + WIN_OFS;
    const __nv_bfloat16* BL = g_bt_lo + WIN_OFS;
    loadB(BH, BL, 256, INDIM, 0, 0);
    loadB(BH, BL, 256, INDIM, 1, 1);
    float acc[2][8][4];
    #pragma unroll
    for (int mi=0;mi<2;mi++)
      #pragma unroll
      for (int j=0;j<8;j++)
        #pragma unroll
        for (int q=0;q<4;q++) acc[mi][j][q]=0.f;
    CP_WAIT(0);
    __syncthreads();
    warp_mma_chunk(acc, sb+HHI,      sb+HLO,      sb+BST,       sb+BST+16384,       wm, wn, lane);
    warp_mma_chunk(acc, sb+HHI+8192, sb+HLO+8192, sb+BST+32768, sb+BST+32768+16384, wm, wn, lane);
    __syncthreads();

    #pragma unroll
    for (int j=0;j<8;j++){
      int col = wn*64 + j*8 + 2*(lane&3);
      float b0 = prm[col], b1 = prm[col+1];
      int p = wn*2 + (j>>2), qj = j&3;
      #pragma unroll
      for (int mi=0;mi<2;mi++){
        #pragma unroll
        for (int h=0;h<2;h++){
          int rl = wm*32 + mi*16 + (lane>>2) + h*8;
          uint32_t adr = (uint32_t)p*8192 + swz(rl, qj) + 4*(lane&3);
          uint32_t whi, wlo;
          split2(acc[mi][j][h*2]+b0, acc[mi][j][h*2+1]+b1, whi, wlo);
          *(uint32_t*)(smem + HHI + adr) = whi;
          *(uint32_t*)(smem + HLO + adr) = wlo;
        }
      }
    }
    __syncthreads();
  }

  // ================= layers 1..3: h += relu(LN(h @ Wb + bb)) =================
  for (int L=0; L<3; L++){
    const __nv_bfloat16* BH = g_bt_hi + (size_t)L*HID*HID;
    const __nv_bfloat16* BL = g_bt_lo + (size_t)L*HID*HID;
    if (tid < 256){
      prm[tid]     = bb [L*HID+tid];
      prm[256+tid] = lng[L*HID+tid];
      prm[512+tid] = lnb[L*HID+tid];
    }
    loadB(BH, BL, 256, HID, 0, 0);
    loadB(BH, BL, 256, HID, 1, 1);

    float acc[2][8][4];
    #pragma unroll
    for (int mi=0;mi<2;mi++)
      #pragma unroll
      for (int j=0;j<8;j++)
        #pragma unroll
        for (int q=0;q<4;q++) acc[mi][j][q]=0.f;

    for (int c=0;c<8;c++){
      if (c<6) { CP_WAIT(1); } else { CP_WAIT(0); }
      __syncthreads();
      uint32_t bbase = sb + BST + (uint32_t)(c&1)*32768;
      warp_mma_chunk(acc, sb+HHI+(uint32_t)c*8192, sb+HLO+(uint32_t)c*8192,
                     bbase, bbase+16384, wm, wn, lane);
      __syncthreads();
      if (c<6) loadB(BH, BL, 256, HID, c+2, c&1);
    }

    float sum[4]={0.f,0.f,0.f,0.f}, ssq[4]={0.f,0.f,0.f,0.f};
    #pragma unroll
    for (int j=0;j<8;j++){
      int col = wn*64 + j*8 + 2*(lane&3);
      float b0 = prm[col], b1 = prm[col+1];
      #pragma unroll
      for (int mi=0;mi<2;mi++){
        acc[mi][j][0]+=b0; acc[mi][j][1]+=b1; acc[mi][j][2]+=b0; acc[mi][j][3]+=b1;
        sum[mi*2+0] += acc[mi][j][0]+acc[mi][j][1];
        ssq[mi*2+0] += acc[mi][j][0]*acc[mi][j][0]+acc[mi][j][1]*acc[mi][j][1];
        sum[mi*2+1] += acc[mi][j][2]+acc[mi][j][3];
        ssq[mi*2+1] += acc[mi][j][2]*acc[mi][j][2]+acc[mi][j][3]*acc[mi][j][3];
      }
    }
    #pragma unroll
    for (int s=0;s<4;s++){
      sum[s]+=__shfl_xor_sync(0xffffffffu,sum[s],1);
      sum[s]+=__shfl_xor_sync(0xffffffffu,sum[s],2);
      ssq[s]+=__shfl_xor_sync(0xffffffffu,ssq[s],1);
      ssq[s]+=__shfl_xor_sync(0xffffffffu,ssq[s],2);
    }
    if ((lane&3)==0){
      #pragma unroll
      for (int mi=0;mi<2;mi++)
        #pragma unroll
        for (int h=0;h<2;h++){
          int row = wm*32 + mi*16 + (lane>>2) + h*8;
          part[(row*4+wn)*2]   = sum[mi*2+h];
          part[(row*4+wn)*2+1] = ssq[mi*2+h];
        }
    }
    __syncthreads();
    float mu[4], rs[4];
    #pragma unroll
    for (int mi=0;mi<2;mi++)
      #pragma unroll
      for (int h=0;h<2;h++){
        int row = wm*32 + mi*16 + (lane>>2) + h*8;
        float s1 = part[(row*4+0)*2]+part[(row*4+1)*2]+part[(row*4+2)*2]+part[(row*4+3)*2];
        float s2 = part[(row*4+0)*2+1]+part[(row*4+1)*2+1]+part[(row*4+2)*2+1]+part[(row*4+3)*2+1];
        int s = mi*2+h;
        mu[s] = s1*(1.f/256.f);
        float var = s2*(1.f/256.f) - mu[s]*mu[s];
        rs[s] = rsqrtf(fmaxf(var,0.f) + LN_EPS);
      }
    #pragma unroll
    for (int j=0;j<8;j++){
      int col = wn*64 + j*8 + 2*(lane&3);
      float lg0 = prm[256+col], lg1 = prm[256+col+1];
      float lb0 = prm[512+col], lb1 = prm[512+col+1];
      int p = wn*2 + (j>>2), qj = j&3;
      #pragma unroll
      for (int mi=0;mi<2;mi++){
        #pragma unroll
        for (int h=0;h<2;h++){
          int rl = wm*32 + mi*16 + (lane>>2) + h*8;
          int s = mi*2+h;
          uint32_t adr = (uint32_t)p*8192 + swz(rl, qj) + 4*(lane&3);
          uint32_t ohh = *(uint32_t*)(smem + HHI + adr);
          uint32_t oll = *(uint32_t*)(smem + HLO + adr);
          float old0 = bf_lo(ohh) + bf_lo(oll);
          float old1 = bf_hi(ohh) + bf_hi(oll);
          float t0 = fmaxf((acc[mi][j][h*2]  -mu[s])*rs[s]*lg0 + lb0, 0.f);
          float t1 = fmaxf((acc[mi][j][h*2+1]-mu[s])*rs[s]*lg1 + lb1, 0.f);
          uint32_t whi, wlo;
          split2(old0+t0, old1+t1, whi, wlo);
          *(uint32_t*)(smem + HHI + adr) = whi;
          *(uint32_t*)(smem + HLO + adr) = wlo;
        }
      }
    }
    __syncthreads();
  }

  // ================= out layer: z = LN(h @ W_out + b_out), sq =================
  {
    const __nv_bfloat16* BH = g_bt_hi + WOUT_OFS;
    const __nv_bfloat16* BL = g_bt_lo + WOUT_OFS;
    if (tid < 128){
      prm[tid]     = bo[tid];
      prm[256+tid] = lnf_g[tid];
      prm[512+tid] = lnf_b[tid];
    }
    loadB(BH, BL, 128, HID, 0, 0);
    loadB(BH, BL, 128, HID, 1, 1);

    float acc[2][4][4];
    #pragma unroll
    for (int mi=0;mi<2;mi++)
      #pragma unroll
      for (int j=0;j<4;j++)
        #pragma unroll
        for (int q=0;q<4;q++) acc[mi][j][q]=0.f;

    for (int c=0;c<8;c++){
      if (c<6) { CP_WAIT(1); } else { CP_WAIT(0); }
      __syncthreads();
      uint32_t bbase = sb + BST + (uint32_t)(c&1)*32768;
      warp_mma_chunk32(acc, sb+HHI+(uint32_t)c*8192, sb+HLO+(uint32_t)c*8192,
                       bbase, bbase+16384, wm, wn, lane);
      __syncthreads();
      if (c<6) loadB(BH, BL, 128, HID, c+2, c&1);
    }

    float sum[4]={0.f,0.f,0.f,0.f}, ssq[4]={0.f,0.f,0.f,0.f};
    #pragma unroll
    for (int j=0;j<4;j++){
      int col = wn*32 + j*8 + 2*(lane&3);
      float b0 = prm[col], b1 = prm[col+1];
      #pragma unroll
      for (int mi=0;mi<2;mi++){
        acc[mi][j][0]+=b0; acc[mi][j][1]+=b1; acc[mi][j][2]+=b0; acc[mi][j][3]+=b1;
        sum[mi*2+0] += acc[mi][j][0]+acc[mi][j][1];
        ssq[mi*2+0] += acc[mi][j][0]*acc[mi][j][0]+acc[mi][j][1]*acc[mi][j][1];
        sum[mi*2+1] += acc[mi][j][2]+acc[mi][j][3];
        ssq[mi*2+1] += acc[mi][j][2]*acc[mi][j][2]+acc[mi][j][3]*acc[mi][j][3];
      }
    }
    #pragma unroll
    for (int s=0;s<4;s++){
      sum[s]+=__shfl_xor_sync(0xffffffffu,sum[s],1);
      sum[s]+=__shfl_xor_sync(0xffffffffu,sum[s],2);
      ssq[s]+=__shfl_xor_sync(0xffffffffu,ssq[s],1);
      ssq[s]+=__shfl_xor_sync(0xffffffffu,ssq[s],2);
    }
    if ((lane&3)==0){
      #pragma unroll
      for (int mi=0;mi<2;mi++)
        #pragma unroll
        for (int h=0;h<2;h++){
          int row = wm*32 + mi*16 + (lane>>2) + h*8;
          part[(row*4+wn)*2]   = sum[mi*2+h];
          part[(row*4+wn)*2+1] = ssq[mi*2+h];
        }
    }
    __syncthreads();
    float mu[4], rs[4];
    #pragma unroll
    for (int mi=0;mi<2;mi++)
      #pragma unroll
      for (int h=0;h<2;h++){
        int row = wm*32 + mi*16 + (lane>>2) + h*8;
        float s1 = part[(row*4+0)*2]+part[(row*4+1)*2]+part[(row*4+2)*2]+part[(row*4+3)*2];
        float s2 = part[(row*4+0)*2+1]+part[(row*4+1)*2+1]+part[(row*4+2)*2+1]+part[(row*4+3)*2+1];
        int s = mi*2+h;
        mu[s] = s1*(1.f/128.f);
        float var = s2*(1.f/128.f) - mu[s]*mu[s];
        rs[s] = rsqrtf(fmaxf(var,0.f) + LN_EPS);
      }
    float qs[4]={0.f,0.f,0.f,0.f};
    #pragma unroll
    for (int j=0;j<4;j++){
      int col = wn*32 + j*8 + 2*(lane&3);
      float lg0 = prm[256+col], lg1 = prm[256+col+1];
      float lb0 = prm[512+col], lb1 = prm[512+col+1];
      #pragma unroll
      for (int mi=0;mi<2;mi++){
        #pragma unroll
        for (int h=0;h<2;h++){
          int rl = wm*32 + mi*16 + (lane>>2) + h*8;
          int s = mi*2+h;
          float t0 = (acc[mi][j][h*2]  -mu[s])*rs[s]*lg0 + lb0;
          float t1 = (acc[mi][j][h*2+1]-mu[s])*rs[s]*lg1 + lb1;
          qs[s] += t0*t0 + t1*t1;
          uint32_t whi, wlo;
          split2(t0, t1, whi, wlo);
          size_t gi = (size_t)(row0+rl)*EMB + col;
          *(uint32_t*)(g_zh + gi) = whi;
          *(uint32_t*)(g_zl + gi) = wlo;
        }
      }
    }
    __syncthreads();
    #pragma unroll
    for (int s=0;s<4;s++){
      qs[s]+=__shfl_xor_sync(0xffffffffu,qs[s],1);
      qs[s]+=__shfl_xor_sync(0xffffffffu,qs[s],2);
    }
    if ((lane&3)==0){
      #pragma unroll
      for (int mi=0;mi<2;mi++)
        #pragma unroll
        for (int h=0;h<2;h++){
          int row = wm*32 + mi*16 + (lane>>2) + h*8;
          part[row*4+wn] = qs[mi*2+h];
        }
    }
    __syncthreads();
    if (wn==0 && (lane&3)==0){
      #pragma unroll
      for (int mi=0;mi<2;mi++)
        #pragma unroll
        for (int h=0;h<2;h++){
          int row = wm*32 + mi*16 + (lane>>2) + h*8;
          g_sq[row0+row] = part[row*4+0]+part[row*4+1]+part[row*4+2]+part[row*4+3];
        }
    }
  }
}

// ---------------------------------------------------------------------------
// k_gram_mma: bf16x3 with dual accumulators.
// SMEM: A hi [0,16K), A lo [16K,32K), B hi [32K,48K), B lo [48K,64K).
// ---------------------------------------------------------------------------
#define GRM_SMEM 65536
__global__ void __launch_bounds__(128) k_gram_mma()
{
  extern __shared__ char smem[];
  const uint32_t sb = smem_u32(smem);
  const int tid = threadIdx.x, lane = tid&31, wid = tid>>5;
  const int wm = wid>>1, wn = wid&1;

  int t = blockIdx.x, rt = 0;
  while (t >= 8 - rt){ t -= 8 - rt; rt++; }
  const int ct = rt + t;
  const bool diag = (rt == ct);
  const int bofs = blockIdx.y * HALF;
  const int r0 = bofs + rt*64;
  const int c0 = bofs + ct*64;

  #pragma unroll
  for (int u=0; u<8; u++){
    int e = tid + u*128;
    int r = e>>4, tt = e&15;
    int c = tt>>2, q = tt&3;
    uint32_t off = (uint32_t)(c*4096) + swz(r, q);
    size_t gi = (size_t)(r0+r)*EMB + c*32 + q*8;
    cp16(sb + off,         g_zh + gi);
    cp16(sb + 16384 + off, g_zl + gi);
  }
  if (!diag){
    #pragma unroll
    for (int u=0; u<8; u++){
      int e = tid + u*128;
      int r = e>>4, tt = e&15;
      int c = tt>>2, q = tt&3;
      uint32_t off = (uint32_t)(c*4096) + swz(r, q);
      size_t gi = (size_t)(c0+r)*EMB + c*32 + q*8;
      cp16(sb + 32768 + off, g_zh + gi);
      cp16(sb + 49152 + off, g_zl + gi);
    }
  }
  CP_COMMIT(); CP_WAIT(0);
  __syncthreads();

  const uint32_t bHb = diag ? sb : (sb + 32768);
  const uint32_t bLb = diag ? (sb + 16384) : (sb + 49152);

  float acc[2][4][4], acc2[2][4][4];
  #pragma unroll
  for (int mi=0;mi<2;mi++)
    #pragma unroll
    for (int j=0;j<4;j++)
      #pragma unroll
      for (int q=0;q<4;q++){ acc[mi][j][q]=0.f; acc2[mi][j][q]=0.f; }

  #pragma unroll
  for (int c=0;c<4;c++)
    warp_mma_gram3(acc, acc2, sb + c*4096, sb + 16384 + c*4096,
                   bHb + c*4096, bLb + c*4096, wm, wn, lane);

  float sqr[4];
  #pragma unroll
  for (int mi=0;mi<2;mi++)
    #pragma unroll
    for (int h=0;h<2;h++)
      sqr[mi*2+h] = g_sq[r0 + wm*32 + mi*16 + (lane>>2) + h*8];

  float rsum[4] = {0.f,0.f,0.f,0.f};
  float csum[8] = {0.f,0.f,0.f,0.f,0.f,0.f,0.f,0.f};
  #pragma unroll
  for (int j=0;j<4;j++){
    int colg = c0 + wn*32 + j*8 + 2*(lane&3);
    float sqc0 = g_sq[colg], sqc1 = g_sq[colg+1];
    #pragma unroll
    for (int mi=0;mi<2;mi++){
      float v0 = acc[mi][j][0]+acc2[mi][j][0];
      float v1 = acc[mi][j][1]+acc2[mi][j][1];
      float v2 = acc[mi][j][2]+acc2[mi][j][2];
      float v3 = acc[mi][j][3]+acc2[mi][j][3];
      float d0 = sqrtf(fmaxf(sqr[mi*2+0] + sqc0 - 2.f*v0, 1e-12f));
      float d1 = sqrtf(fmaxf(sqr[mi*2+0] + sqc1 - 2.f*v1, 1e-12f));
      float d2 = sqrtf(fmaxf(sqr[mi*2+1] + sqc0 - 2.f*v2, 1e-12f));
      float d3 = sqrtf(fmaxf(sqr[mi*2+1] + sqc1 - 2.f*v3, 1e-12f));
      rsum[mi*2+0] += d0 + d1;
      rsum[mi*2+1] += d2 + d3;
      csum[j*2+0]  += d0 + d2;
      csum[j*2+1]  += d1 + d3;
    }
  }

  #pragma unroll
  for (int i=0;i<4;i++){
    rsum[i] += __shfl_xor_sync(0xffffffffu, rsum[i], 1);
    rsum[i] += __shfl_xor_sync(0xffffffffu, rsum[i], 2);
  }
  if ((lane & 3) == 0){
    #pragma unroll
    for (int mi=0;mi<2;mi++)
      #pragma unroll
      for (int h=0;h<2;h++)
        atomicAdd(&g_s[r0 + wm*32 + mi*16 + (lane>>2) + h*8], rsum[mi*2+h]);
  }

  if (!diag){
    #pragma unroll
    for (int i=0;i<8;i++){
      csum[i] += __shfl_xor_sync(0xffffffffu, csum[i], 4);
      csum[i] += __shfl_xor_sync(0xffffffffu, csum[i], 8);
      csum[i] += __shfl_xor_sync(0xffffffffu, csum[i], 16);
    }
    if ((lane >> 2) == 0){
      #pragma unroll
      for (int j=0;j<4;j++){
        int colg = c0 + wn*32 + j*8 + 2*(lane&3);
        atomicAdd(&g_s[colg],   csum[j*2+0]);
        atomicAdd(&g_s[colg+1], csum[j*2+1]);
      }
    }
  }
}

// ---------------------------------------------------------------------------
// k_softmax: per batch softmax over 512 unique scores; write w output,
// normalized weights to g_w, zero the f region of out.
// ---------------------------------------------------------------------------
__global__ void __launch_bounds__(256) k_softmax(
    const int* __restrict__ pairs, float* __restrict__ out)
{
  __shared__ float red[256];
  const int b = blockIdx.x, tid = threadIdx.x;
  const float scale = 1.f/(512.f*0.25f);
  float x0 = g_s[b*HALF + tid      ]*scale;
  float x1 = g_s[b*HALF + 256 + tid]*scale;

  red[tid] = fmaxf(x0,x1);
  __syncthreads();
  for (int o=128;o;o>>=1){ if(tid<o) red[tid]=fmaxf(red[tid],red[tid+o]); __syncthreads(); }
  float mx = red[0];
  __syncthreads();

  float e0 = expf(x0-mx), e1 = expf(x1-mx);
  red[tid] = e0+e1;
  __syncthreads();
  for (int o=128;o;o>>=1){ if(tid<o) red[tid]+=red[tid+o]; __syncthreads(); }
  float inv = 1.f/red[0];

  float w0 = e0*inv, w1 = e1*inv;
  g_w[b*HALF + tid]       = w0;
  g_w[b*HALF + 256 + tid] = w1;

  float* wout = out + NBATCH*EMB;
  {
    int p = b*HALF + tid;
    wout[pairs[2*p]]   = w0*0.5f;
    wout[pairs[2*p+1]] = w0*0.5f;
    p = b*HALF + 256 + tid;
    wout[pairs[2*p]]   = w1*0.5f;
    wout[pairs[2*p+1]] = w1*0.5f;
  }
  if (tid < EMB) out[b*EMB + tid] = 0.f;
}

// ---------------------------------------------------------------------------
// k_fsum v2: f[b] += sum over a 64-row slice of w[i] * z[i]. grid (8, NBATCH).
// Thread owns 4 columns (uint2 loads) over an 8-row sub-slice: short chains,
// 512 CTAs of parallelism.
// ---------------------------------------------------------------------------
__global__ void __launch_bounds__(256) k_fsum(float* __restrict__ out)
{
  __shared__ float wsh[64];
  __shared__ float red[256*4];
  const int b = blockIdx.y, tid = threadIdx.x;
  const int base = b*HALF + blockIdx.x*64;
  if (tid < 64) wsh[tid] = g_w[base + tid];
  __syncthreads();

  const int c4 = (tid & 31)*4;   // 4-column group
  const int p  = tid >> 5;       // 0..7 row sub-slice (8 rows each)
  float f[4] = {0.f,0.f,0.f,0.f};
  #pragma unroll
  for (int r=0; r<8; r++){
    int ii = p*8 + r;
    float w = wsh[ii];
    size_t gi = (size_t)(base + ii)*EMB + c4;
    uint2 zh = *(const uint2*)(g_zh + gi);
    uint2 zl = *(const uint2*)(g_zl + gi);
    f[0] = fmaf(w, bf_lo(zh.x) + bf_lo(zl.x), f[0]);
    f[1] = fmaf(w, bf_hi(zh.x) + bf_hi(zl.x), f[1]);
    f[2] = fmaf(w, bf_lo(zh.y) + bf_lo(zl.y), f[2]);
    f[3] = fmaf(w, bf_hi(zh.y) + bf_hi(zl.y), f[3]);
  }
  #pragma unroll
  for (int q=0;q<4;q++) red[tid*4+q] = f[q];
  __syncthreads();
  if (tid < 32){
    float a[4] = {0.f,0.f,0.f,0.f};
    #pragma unroll
    for (int pp=0; pp<8; pp++)
      #pragma unroll
      for (int q=0;q<4;q++)
        a[q] += red[(pp*32+tid)*4+q];
    #pragma unroll
    for (int q=0;q<4;q++)
      atomicAdd(&out[b*EMB + tid*4 + q], a[q]);
  }
}

// ---------------------------------------------------------------------------
extern "C" void kernel_launch(void* const* d_in, const int* in_sizes, int n_in,
                              void* d_out, int out_size)
{
  const float* H     = (const float*)d_in[0];
  const int*   pairs = (const int*)  d_in[2];
  const float* W_in  = (const float*)d_in[3];
  const float* b_in  = (const float*)d_in[4];
  const float* Wb    = (const float*)d_in[5];
  const float* bb    = (const float*)d_in[6];
  const float* lng   = (const float*)d_in[7];
  const float* lnb   = (const float*)d_in[8];
  const float* W_out = (const float*)d_in[9];
  const float* b_out = (const float*)d_in[10];
  const float* lnf_g = (const float*)d_in[11];
  const float* lnf_b = (const float*)d_in[12];
  float* out = (float*)d_out;

  cudaFuncSetAttribute(k_mega,     cudaFuncAttributeMaxDynamicSharedMemorySize, MEGA_SMEM);
  cudaFuncSetAttribute(k_gram_mma, cudaFuncAttributeMaxDynamicSharedMemorySize, GRM_SMEM);

  k_prep<<<(WT_TOTAL + 255)/256, 256>>>(Wb, W_out, W_in);
  k_mega<<<MROWS/128, 512, MEGA_SMEM>>>(H, pairs, b_in, bb, lng, lnb,
                                        b_out, lnf_g, lnf_b);
  k_gram_mma<<<dim3(36, NBATCH), 128, GRM_SMEM>>>();
  k_softmax<<<NBATCH, 256>>>(pairs, out);
  k_fsum<<<dim3(8, NBATCH), 256>>>(out);
}

// round 15
// speedup vs baseline: 1.3263x; 1.0633x over previous
#include <cuda_runtime.h>
#include <cuda_bf16.h>
#include <math.h>
#include <stdint.h>

#define NBATCH 64
#define HALF   512
#define INDIM  64
#define HID    256
#define EMB    128
#define MROWS  (NBATCH*HALF)   // 32768 unique rows
#define LN_EPS 1e-5f

// weight regions inside g_bt_*
#define WOUT_OFS (3*HID*HID)
#define WIN_OFS  (3*HID*HID + EMB*HID)
#define WT_TOTAL (WIN_OFS + HID*INDIM)

// ---------------- device scratch (allocation is forbidden) ------------------
__device__ __align__(16) __nv_bfloat16 g_bt_hi[WT_TOTAL];
__device__ __align__(16) __nv_bfloat16 g_bt_lo[WT_TOTAL];
__device__ __align__(16) __nv_bfloat16 g_zh[MROWS*EMB];   // z hi
__device__ __align__(16) __nv_bfloat16 g_zl[MROWS*EMB];   // z lo
__device__ float g_sq[MROWS];
__device__ float g_s [MROWS];
__device__ float g_w [MROWS];   // normalized softmax weights (unique rows)

// ---------------- helpers ----------------------------------------------------
__device__ __forceinline__ uint32_t smem_u32(const void* p){
  uint32_t a;
  asm("{ .reg .u64 t; cvta.to.shared.u64 t, %1; cvt.u32.u64 %0, t; }" : "=r"(a) : "l"(p));
  return a;
}
__device__ __forceinline__ void cp16(uint32_t dst, const void* src){
  asm volatile("cp.async.cg.shared.global [%0], [%1], 16;\n" :: "r"(dst), "l"(src));
}
#define CP_COMMIT() asm volatile("cp.async.commit_group;\n" ::: "memory")
#define CP_WAIT(n)  asm volatile("cp.async.wait_group %0;\n" :: "n"(n) : "memory")

__device__ __forceinline__ void ldsm4(uint32_t (&r)[4], uint32_t addr){
  asm volatile("ldmatrix.sync.aligned.m8n8.x4.shared.b16 {%0,%1,%2,%3}, [%4];\n"
    : "=r"(r[0]),"=r"(r[1]),"=r"(r[2]),"=r"(r[3]) : "r"(addr));
}
__device__ __forceinline__ void mma16816(float (&d)[4], const uint32_t (&a)[4],
                                         uint32_t b0, uint32_t b1){
  asm volatile("mma.sync.aligned.m16n8k16.row.col.f32.bf16.bf16.f32 "
    "{%0,%1,%2,%3}, {%4,%5,%6,%7}, {%8,%9}, {%0,%1,%2,%3};\n"
    : "+f"(d[0]),"+f"(d[1]),"+f"(d[2]),"+f"(d[3])
    : "r"(a[0]),"r"(a[1]),"r"(a[2]),"r"(a[3]), "r"(b0),"r"(b1));
}
// rows of 64B (32 bf16); 16B column-chunk c in 0..3; XOR swizzle
__device__ __forceinline__ uint32_t swz(int r, int c){
  return (uint32_t)(r*64 + ((c ^ ((r>>1)&3))<<4));
}
__device__ __forceinline__ void split_bf16(float x, __nv_bfloat16& h, __nv_bfloat16& l){
  h = __float2bfloat16(x);
  l = __float2bfloat16(x - __bfloat162float(h));
}
__device__ __forceinline__ void split2(float v0, float v1, uint32_t& whi, uint32_t& wlo){
  __nv_bfloat16 h0,l0,h1,l1;
  split_bf16(v0,h0,l0); split_bf16(v1,h1,l1);
  whi = ((uint32_t)__bfloat16_as_ushort(h1)<<16) | (uint32_t)__bfloat16_as_ushort(h0);
  wlo = ((uint32_t)__bfloat16_as_ushort(l1)<<16) | (uint32_t)__bfloat16_as_ushort(l0);
}
__device__ __forceinline__ float bf_lo(uint32_t w){
  return __bfloat162float(__ushort_as_bfloat16((unsigned short)(w & 0xffffu)));
}
__device__ __forceinline__ float bf_hi(uint32_t w){
  return __bfloat162float(__ushort_as_bfloat16((unsigned short)(w >> 16)));
}

// warp tile 32 rows x 64 cols, one k32 chunk, bf16x3 accumulate
__device__ __forceinline__ void warp_mma_chunk(
    float (&acc)[2][8][4],
    uint32_t aH, uint32_t aL, uint32_t bH, uint32_t bL,
    int wm, int wn, int lane)
{
  #pragma unroll
  for (int kk=0; kk<2; kk++){
    uint32_t ah[2][4], al[2][4];
    #pragma unroll
    for (int mi=0; mi<2; mi++){
      int row = wm*32 + mi*16 + (lane & 15);
      int c   = kk*2 + (lane >> 4);
      uint32_t off = swz(row, c);
      ldsm4(ah[mi], aH + off);
      ldsm4(al[mi], aL + off);
    }
    #pragma unroll
    for (int p=0; p<4; p++){
      int n = wn*64 + p*16 + ((lane>>4)<<3) + (lane & 7);
      int c = kk*2 + ((lane>>3)&1);
      uint32_t off = swz(n, c);
      uint32_t bh[4], bl[4];
      ldsm4(bh, bH + off);
      ldsm4(bl, bL + off);
      #pragma unroll
      for (int mi=0; mi<2; mi++){
        #pragma unroll
        for (int h=0; h<2; h++){
          mma16816(acc[mi][p*2+h], ah[mi], bh[2*h], bh[2*h+1]);
          mma16816(acc[mi][p*2+h], ah[mi], bl[2*h], bl[2*h+1]);
          mma16816(acc[mi][p*2+h], al[mi], bh[2*h], bh[2*h+1]);
        }
      }
    }
  }
}

// warp tile 32 rows x 32 cols, one k32 chunk, bf16x3
__device__ __forceinline__ void warp_mma_chunk32(
    float (&acc)[2][4][4],
    uint32_t aH, uint32_t aL, uint32_t bH, uint32_t bL,
    int wm, int wn, int lane)
{
  #pragma unroll
  for (int kk=0; kk<2; kk++){
    uint32_t ah[2][4], al[2][4];
    #pragma unroll
    for (int mi=0; mi<2; mi++){
      int row = wm*32 + mi*16 + (lane & 15);
      int c   = kk*2 + (lane >> 4);
      uint32_t off = swz(row, c);
      ldsm4(ah[mi], aH + off);
      ldsm4(al[mi], aL + off);
    }
    #pragma unroll
    for (int p=0; p<2; p++){
      int n = wn*32 + p*16 + ((lane>>4)<<3) + (lane & 7);
      int c = kk*2 + ((lane>>3)&1);
      uint32_t off = swz(n, c);
      uint32_t bh[4], bl[4];
      ldsm4(bh, bH + off);
      ldsm4(bl, bL + off);
      #pragma unroll
      for (int mi=0; mi<2; mi++){
        #pragma unroll
        for (int h=0; h<2; h++){
          mma16816(acc[mi][p*2+h], ah[mi], bh[2*h], bh[2*h+1]);
          mma16816(acc[mi][p*2+h], ah[mi], bl[2*h], bl[2*h+1]);
          mma16816(acc[mi][p*2+h], al[mi], bh[2*h], bh[2*h+1]);
        }
      }
    }
  }
}

// gram bf16x3 with dual accumulators
__device__ __forceinline__ void warp_mma_gram3(
    float (&acc)[2][4][4], float (&acc2)[2][4][4],
    uint32_t aH, uint32_t aL, uint32_t bH, uint32_t bL,
    int wm, int wn, int lane)
{
  #pragma unroll
  for (int kk=0; kk<2; kk++){
    uint32_t ah[2][4], al[2][4];
    #pragma unroll
    for (int mi=0; mi<2; mi++){
      int row = wm*32 + mi*16 + (lane & 15);
      int c   = kk*2 + (lane >> 4);
      uint32_t off = swz(row, c);
      ldsm4(ah[mi], aH + off);
      ldsm4(al[mi], aL + off);
    }
    #pragma unroll
    for (int p=0; p<2; p++){
      int n = wn*32 + p*16 + ((lane>>4)<<3) + (lane & 7);
      int c = kk*2 + ((lane>>3)&1);
      uint32_t off = swz(n, c);
      uint32_t bh[4], bl[4];
      ldsm4(bh, bH + off);
      ldsm4(bl, bL + off);
      #pragma unroll
      for (int mi=0; mi<2; mi++){
        #pragma unroll
        for (int h=0; h<2; h++){
          mma16816(acc [mi][p*2+h], ah[mi], bh[2*h], bh[2*h+1]);
          mma16816(acc2[mi][p*2+h], ah[mi], bl[2*h], bl[2*h+1]);
          mma16816(acc2[mi][p*2+h], al[mi], bh[2*h], bh[2*h+1]);
        }
      }
    }
  }
}

// ---------------------------------------------------------------------------
// prep: transpose + hi/lo split of Wb, W_out, W_in; zero g_s
// ---------------------------------------------------------------------------
__global__ void __launch_bounds__(256) k_prep(
    const float* __restrict__ Wb, const float* __restrict__ Wout,
    const float* __restrict__ Win)
{
  int i = blockIdx.x*256 + threadIdx.x;
  if (i < MROWS) g_s[i] = 0.f;
  float v;
  if (i < WOUT_OFS){
    int layer = i >> 16;
    int n  = (i >> 8) & 255;
    int kk = i & 255;
    v = Wb[layer*HID*HID + kk*HID + n];
  } else if (i < WIN_OFS){
    int j = i - WOUT_OFS;
    int n  = j >> 8;
    int kk = j & 255;
    v = Wout[kk*EMB + n];
  } else if (i < WT_TOTAL){
    int j = i - WIN_OFS;
    int n  = j >> 6;
    int kk = j & 63;
    v = Win[kk*HID + n];
  } else return;
  __nv_bfloat16 h, l; split_bf16(v, h, l);
  g_bt_hi[i] = h; g_bt_lo[i] = l;
}

// ---------------------------------------------------------------------------
// k_mega (proven config + cta_base for split launch)
// ---------------------------------------------------------------------------
#define HHI  0
#define HLO  65536
#define BST  131072
#define PRM  196608
#define PART 199680
#define IDX  203776
#define MEGA_SMEM 204800

__global__ void __launch_bounds__(512) k_mega(
    int cta_base,
    const float* __restrict__ H, const int* __restrict__ pairs,
    const float* __restrict__ b_in,
    const float* __restrict__ bb, const float* __restrict__ lng,
    const float* __restrict__ lnb,
    const float* __restrict__ bo, const float* __restrict__ lnf_g,
    const float* __restrict__ lnf_b)
{
  extern __shared__ char smem[];
  const uint32_t sb = smem_u32(smem);
  const int tid = threadIdx.x, lane = tid&31, wid = tid>>5;
  const int wm = wid>>2, wn = wid&3;
  const int row0 = (cta_base + blockIdx.x) * 128;
  int*   li   = (int*)(smem + IDX);
  int*   ri   = li + 128;
  float* prm  = (float*)(smem + PRM);
  float* part = (float*)(smem + PART);

  if (tid < 128){
    li[tid] = pairs[2*(row0+tid)];
    ri[tid] = pairs[2*(row0+tid)+1];
  }
  if (tid < 256) prm[tid] = b_in[tid];
  __syncthreads();

  // ---- delta = |H[li]-H[ri]| into h planes 0,1 (K=64) ----
  #pragma unroll
  for (int u=0; u<2; u++){
    int e = tid + u*512;
    int r = e>>3, g = e&7;
    const float* pl = H + (size_t)li[r]*INDIM + g*8;
    const float* pr = H + (size_t)ri[r]*INDIM + g*8;
    float4 a0 = *(const float4*)pl,     a1 = *(const float4*)(pl+4);
    float4 b0 = *(const float4*)pr,     b1 = *(const float4*)(pr+4);
    float d0=fabsf(a0.x-b0.x), d1=fabsf(a0.y-b0.y), d2=fabsf(a0.z-b0.z), d3=fabsf(a0.w-b0.w);
    float d4=fabsf(a1.x-b1.x), d5=fabsf(a1.y-b1.y), d6=fabsf(a1.z-b1.z), d7=fabsf(a1.w-b1.w);
    uint32_t h0,h1,h2,h3,l0,l1,l2,l3;
    split2(d0,d1,h0,l0); split2(d2,d3,h1,l1);
    split2(d4,d5,h2,l2); split2(d6,d7,h3,l3);
    uint32_t off = (uint32_t)((g>>2)*8192) + swz(r, g&3);
    *(uint4*)(smem + HHI + off) = make_uint4(h0,h1,h2,h3);
    *(uint4*)(smem + HLO + off) = make_uint4(l0,l1,l2,l3);
  }

  auto loadB = [&](const __nv_bfloat16* BH, const __nv_bfloat16* BL,
                   int nrows, int kstride, int c, int s){
    uint32_t base = sb + BST + (uint32_t)s*32768;
    int iters = (nrows*4)/512;
    for (int u=0; u<iters; u++){
      int e = tid + u*512;
      int n = e>>2, q = e&3;
      size_t gi = (size_t)n*kstride + c*32 + q*8;
      uint32_t off = swz(n, q);
      cp16(base + off,         BH + gi);
      cp16(base + 16384 + off, BL + gi);
    }
    CP_COMMIT();
  };

  // ================= layer 0: h = delta @ W_in + b_in =================
  {
    const __nv_bfloat16* BH = g_bt_hi + WIN_OFS;
    const __nv_bfloat16* BL = g_bt_lo + WIN_OFS;
    loadB(BH, BL, 256, INDIM, 0, 0);
    loadB(BH, BL, 256, INDIM, 1, 1);
    float acc[2][8][4];
    #pragma unroll
    for (int mi=0;mi<2;mi++)
      #pragma unroll
      for (int j=0;j<8;j++)
        #pragma unroll
        for (int q=0;q<4;q++) acc[mi][j][q]=0.f;
    CP_WAIT(0);
    __syncthreads();
    warp_mma_chunk(acc, sb+HHI,      sb+HLO,      sb+BST,       sb+BST+16384,       wm, wn, lane);
    warp_mma_chunk(acc, sb+HHI+8192, sb+HLO+8192, sb+BST+32768, sb+BST+32768+16384, wm, wn, lane);
    __syncthreads();

    #pragma unroll
    for (int j=0;j<8;j++){
      int col = wn*64 + j*8 + 2*(lane&3);
      float b0 = prm[col], b1 = prm[col+1];
      int p = wn*2 + (j>>2), qj = j&3;
      #pragma unroll
      for (int mi=0;mi<2;mi++){
        #pragma unroll
        for (int h=0;h<2;h++){
          int rl = wm*32 + mi*16 + (lane>>2) + h*8;
          uint32_t adr = (uint32_t)p*8192 + swz(rl, qj) + 4*(lane&3);
          uint32_t whi, wlo;
          split2(acc[mi][j][h*2]+b0, acc[mi][j][h*2+1]+b1, whi, wlo);
          *(uint32_t*)(smem + HHI + adr) = whi;
          *(uint32_t*)(smem + HLO + adr) = wlo;
        }
      }
    }
    __syncthreads();
  }

  // ================= layers 1..3: h += relu(LN(h @ Wb + bb)) =================
  for (int L=0; L<3; L++){
    const __nv_bfloat16* BH = g_bt_hi + (size_t)L*HID*HID;
    const __nv_bfloat16* BL = g_bt_lo + (size_t)L*HID*HID;
    if (tid < 256){
      prm[tid]     = bb [L*HID+tid];
      prm[256+tid] = lng[L*HID+tid];
      prm[512+tid] = lnb[L*HID+tid];
    }
    loadB(BH, BL, 256, HID, 0, 0);
    loadB(BH, BL, 256, HID, 1, 1);

    float acc[2][8][4];
    #pragma unroll
    for (int mi=0;mi<2;mi++)
      #pragma unroll
      for (int j=0;j<8;j++)
        #pragma unroll
        for (int q=0;q<4;q++) acc[mi][j][q]=0.f;

    for (int c=0;c<8;c++){
      if (c<6) { CP_WAIT(1); } else { CP_WAIT(0); }
      __syncthreads();
      uint32_t bbase = sb + BST + (uint32_t)(c&1)*32768;
      warp_mma_chunk(acc, sb+HHI+(uint32_t)c*8192, sb+HLO+(uint32_t)c*8192,
                     bbase, bbase+16384, wm, wn, lane);
      __syncthreads();
      if (c<6) loadB(BH, BL, 256, HID, c+2, c&1);
    }

    float sum[4]={0.f,0.f,0.f,0.f}, ssq[4]={0.f,0.f,0.f,0.f};
    #pragma unroll
    for (int j=0;j<8;j++){
      int col = wn*64 + j*8 + 2*(lane&3);
      float b0 = prm[col], b1 = prm[col+1];
      #pragma unroll
      for (int mi=0;mi<2;mi++){
        acc[mi][j][0]+=b0; acc[mi][j][1]+=b1; acc[mi][j][2]+=b0; acc[mi][j][3]+=b1;
        sum[mi*2+0] += acc[mi][j][0]+acc[mi][j][1];
        ssq[mi*2+0] += acc[mi][j][0]*acc[mi][j][0]+acc[mi][j][1]*acc[mi][j][1];
        sum[mi*2+1] += acc[mi][j][2]+acc[mi][j][3];
        ssq[mi*2+1] += acc[mi][j][2]*acc[mi][j][2]+acc[mi][j][3]*acc[mi][j][3];
      }
    }
    #pragma unroll
    for (int s=0;s<4;s++){
      sum[s]+=__shfl_xor_sync(0xffffffffu,sum[s],1);
      sum[s]+=__shfl_xor_sync(0xffffffffu,sum[s],2);
      ssq[s]+=__shfl_xor_sync(0xffffffffu,ssq[s],1);
      ssq[s]+=__shfl_xor_sync(0xffffffffu,ssq[s],2);
    }
    if ((lane&3)==0){
      #pragma unroll
      for (int mi=0;mi<2;mi++)
        #pragma unroll
        for (int h=0;h<2;h++){
          int row = wm*32 + mi*16 + (lane>>2) + h*8;
          part[(row*4+wn)*2]   = sum[mi*2+h];
          part[(row*4+wn)*2+1] = ssq[mi*2+h];
        }
    }
    __syncthreads();
    float mu[4], rs[4];
    #pragma unroll
    for (int mi=0;mi<2;mi++)
      #pragma unroll
      for (int h=0;h<2;h++){
        int row = wm*32 + mi*16 + (lane>>2) + h*8;
        float s1 = part[(row*4+0)*2]+part[(row*4+1)*2]+part[(row*4+2)*2]+part[(row*4+3)*2];
        float s2 = part[(row*4+0)*2+1]+part[(row*4+1)*2+1]+part[(row*4+2)*2+1]+part[(row*4+3)*2+1];
        int s = mi*2+h;
        mu[s] = s1*(1.f/256.f);
        float var = s2*(1.f/256.f) - mu[s]*mu[s];
        rs[s] = rsqrtf(fmaxf(var,0.f) + LN_EPS);
      }
    #pragma unroll
    for (int j=0;j<8;j++){
      int col = wn*64 + j*8 + 2*(lane&3);
      float lg0 = prm[256+col], lg1 = prm[256+col+1];
      float lb0 = prm[512+col], lb1 = prm[512+col+1];
      int p = wn*2 + (j>>2), qj = j&3;
      #pragma unroll
      for (int mi=0;mi<2;mi++){
        #pragma unroll
        for (int h=0;h<2;h++){
          int rl = wm*32 + mi*16 + (lane>>2) + h*8;
          int s = mi*2+h;
          uint32_t adr = (uint32_t)p*8192 + swz(rl, qj) + 4*(lane&3);
          uint32_t ohh = *(uint32_t*)(smem + HHI + adr);
          uint32_t oll = *(uint32_t*)(smem + HLO + adr);
          float old0 = bf_lo(ohh) + bf_lo(oll);
          float old1 = bf_hi(ohh) + bf_hi(oll);
          float t0 = fmaxf((acc[mi][j][h*2]  -mu[s])*rs[s]*lg0 + lb0, 0.f);
          float t1 = fmaxf((acc[mi][j][h*2+1]-mu[s])*rs[s]*lg1 + lb1, 0.f);
          uint32_t whi, wlo;
          split2(old0+t0, old1+t1, whi, wlo);
          *(uint32_t*)(smem + HHI + adr) = whi;
          *(uint32_t*)(smem + HLO + adr) = wlo;
        }
      }
    }
    __syncthreads();
  }

  // ================= out layer: z = LN(h @ W_out + b_out), sq =================
  {
    const __nv_bfloat16* BH = g_bt_hi + WOUT_OFS;
    const __nv_bfloat16* BL = g_bt_lo + WOUT_OFS;
    if (tid < 128){
      prm[tid]     = bo[tid];
      prm[256+tid] = lnf_g[tid];
      prm[512+tid] = lnf_b[tid];
    }
    loadB(BH, BL, 128, HID, 0, 0);
    loadB(BH, BL, 128, HID, 1, 1);

    float acc[2][4][4];
    #pragma unroll
    for (int mi=0;mi<2;mi++)
      #pragma unroll
      for (int j=0;j<4;j++)
        #pragma unroll
        for (int q=0;q<4;q++) acc[mi][j][q]=0.f;

    for (int c=0;c<8;c++){
      if (c<6) { CP_WAIT(1); } else { CP_WAIT(0); }
      __syncthreads();
      uint32_t bbase = sb + BST + (uint32_t)(c&1)*32768;
      warp_mma_chunk32(acc, sb+HHI+(uint32_t)c*8192, sb+HLO+(uint32_t)c*8192,
                       bbase, bbase+16384, wm, wn, lane);
      __syncthreads();
      if (c<6) loadB(BH, BL, 128, HID, c+2, c&1);
    }

    float sum[4]={0.f,0.f,0.f,0.f}, ssq[4]={0.f,0.f,0.f,0.f};
    #pragma unroll
    for (int j=0;j<4;j++){
      int col = wn*32 + j*8 + 2*(lane&3);
      float b0 = prm[col], b1 = prm[col+1];
      #pragma unroll
      for (int mi=0;mi<2;mi++){
        acc[mi][j][0]+=b0; acc[mi][j][1]+=b1; acc[mi][j][2]+=b0; acc[mi][j][3]+=b1;
        sum[mi*2+0] += acc[mi][j][0]+acc[mi][j][1];
        ssq[mi*2+0] += acc[mi][j][0]*acc[mi][j][0]+acc[mi][j][1]*acc[mi][j][1];
        sum[mi*2+1] += acc[mi][j][2]+acc[mi][j][3];
        ssq[mi*2+1] += acc[mi][j][2]*acc[mi][j][2]+acc[mi][j][3]*acc[mi][j][3];
      }
    }
    #pragma unroll
    for (int s=0;s<4;s++){
      sum[s]+=__shfl_xor_sync(0xffffffffu,sum[s],1);
      sum[s]+=__shfl_xor_sync(0xffffffffu,sum[s],2);
      ssq[s]+=__shfl_xor_sync(0xffffffffu,ssq[s],1);
      ssq[s]+=__shfl_xor_sync(0xffffffffu,ssq[s],2);
    }
    if ((lane&3)==0){
      #pragma unroll
      for (int mi=0;mi<2;mi++)
        #pragma unroll
        for (int h=0;h<2;h++){
          int row = wm*32 + mi*16 + (lane>>2) + h*8;
          part[(row*4+wn)*2]   = sum[mi*2+h];
          part[(row*4+wn)*2+1] = ssq[mi*2+h];
        }
    }
    __syncthreads();
    float mu[4], rs[4];
    #pragma unroll
    for (int mi=0;mi<2;mi++)
      #pragma unroll
      for (int h=0;h<2;h++){
        int row = wm*32 + mi*16 + (lane>>2) + h*8;
        float s1 = part[(row*4+0)*2]+part[(row*4+1)*2]+part[(row*4+2)*2]+part[(row*4+3)*2];
        float s2 = part[(row*4+0)*2+1]+part[(row*4+1)*2+1]+part[(row*4+2)*2+1]+part[(row*4+3)*2+1];
        int s = mi*2+h;
        mu[s] = s1*(1.f/128.f);
        float var = s2*(1.f/128.f) - mu[s]*mu[s];
        rs[s] = rsqrtf(fmaxf(var,0.f) + LN_EPS);
      }
    float qs[4]={0.f,0.f,0.f,0.f};
    #pragma unroll
    for (int j=0;j<4;j++){
      int col = wn*32 + j*8 + 2*(lane&3);
      float lg0 = prm[256+col], lg1 = prm[256+col+1];
      float lb0 = prm[512+col], lb1 = prm[512+col+1];
      #pragma unroll
      for (int mi=0;mi<2;mi++){
        #pragma unroll
        for (int h=0;h<2;h++){
          int rl = wm*32 + mi*16 + (lane>>2) + h*8;
          int s = mi*2+h;
          float t0 = (acc[mi][j][h*2]  -mu[s])*rs[s]*lg0 + lb0;
          float t1 = (acc[mi][j][h*2+1]-mu[s])*rs[s]*lg1 + lb1;
          qs[s] += t0*t0 + t1*t1;
          uint32_t whi, wlo;
          split2(t0, t1, whi, wlo);
          size_t gi = (size_t)(row0+rl)*EMB + col;
          *(uint32_t*)(g_zh + gi) = whi;
          *(uint32_t*)(g_zl + gi) = wlo;
        }
      }
    }
    __syncthreads();
    #pragma unroll
    for (int s=0;s<4;s++){
      qs[s]+=__shfl_xor_sync(0xffffffffu,qs[s],1);
      qs[s]+=__shfl_xor_sync(0xffffffffu,qs[s],2);
    }
    if ((lane&3)==0){
      #pragma unroll
      for (int mi=0;mi<2;mi++)
        #pragma unroll
        for (int h=0;h<2;h++){
          int row = wm*32 + mi*16 + (lane>>2) + h*8;
          part[row*4+wn] = qs[mi*2+h];
        }
    }
    __syncthreads();
    if (wn==0 && (lane&3)==0){
      #pragma unroll
      for (int mi=0;mi<2;mi++)
        #pragma unroll
        for (int h=0;h<2;h++){
          int row = wm*32 + mi*16 + (lane>>2) + h*8;
          g_sq[row0+row] = part[row*4+0]+part[row*4+1]+part[row*4+2]+part[row*4+3];
        }
    }
  }
}

// ---------------------------------------------------------------------------
// k_gram_mma: bf16x3 with dual accumulators; batch_base for split launch.
// ---------------------------------------------------------------------------
#define GRM_SMEM 65536
__global__ void __launch_bounds__(128) k_gram_mma(int batch_base)
{
  extern __shared__ char smem[];
  const uint32_t sb = smem_u32(smem);
  const int tid = threadIdx.x, lane = tid&31, wid = tid>>5;
  const int wm = wid>>1, wn = wid&1;

  int t = blockIdx.x, rt = 0;
  while (t >= 8 - rt){ t -= 8 - rt; rt++; }
  const int ct = rt + t;
  const bool diag = (rt == ct);
  const int bofs = (batch_base + blockIdx.y) * HALF;
  const int r0 = bofs + rt*64;
  const int c0 = bofs + ct*64;

  #pragma unroll
  for (int u=0; u<8; u++){
    int e = tid + u*128;
    int r = e>>4, tt = e&15;
    int c = tt>>2, q = tt&3;
    uint32_t off = (uint32_t)(c*4096) + swz(r, q);
    size_t gi = (size_t)(r0+r)*EMB + c*32 + q*8;
    cp16(sb + off,         g_zh + gi);
    cp16(sb + 16384 + off, g_zl + gi);
  }
  if (!diag){
    #pragma unroll
    for (int u=0; u<8; u++){
      int e = tid + u*128;
      int r = e>>4, tt = e&15;
      int c = tt>>2, q = tt&3;
      uint32_t off = (uint32_t)(c*4096) + swz(r, q);
      size_t gi = (size_t)(c0+r)*EMB + c*32 + q*8;
      cp16(sb + 32768 + off, g_zh + gi);
      cp16(sb + 49152 + off, g_zl + gi);
    }
  }
  CP_COMMIT(); CP_WAIT(0);
  __syncthreads();

  const uint32_t bHb = diag ? sb : (sb + 32768);
  const uint32_t bLb = diag ? (sb + 16384) : (sb + 49152);

  float acc[2][4][4], acc2[2][4][4];
  #pragma unroll
  for (int mi=0;mi<2;mi++)
    #pragma unroll
    for (int j=0;j<4;j++)
      #pragma unroll
      for (int q=0;q<4;q++){ acc[mi][j][q]=0.f; acc2[mi][j][q]=0.f; }

  #pragma unroll
  for (int c=0;c<4;c++)
    warp_mma_gram3(acc, acc2, sb + c*4096, sb + 16384 + c*4096,
                   bHb + c*4096, bLb + c*4096, wm, wn, lane);

  float sqr[4];
  #pragma unroll
  for (int mi=0;mi<2;mi++)
    #pragma unroll
    for (int h=0;h<2;h++)
      sqr[mi*2+h] = g_sq[r0 + wm*32 + mi*16 + (lane>>2) + h*8];

  float rsum[4] = {0.f,0.f,0.f,0.f};
  float csum[8] = {0.f,0.f,0.f,0.f,0.f,0.f,0.f,0.f};
  #pragma unroll
  for (int j=0;j<4;j++){
    int colg = c0 + wn*32 + j*8 + 2*(lane&3);
    float sqc0 = g_sq[colg], sqc1 = g_sq[colg+1];
    #pragma unroll
    for (int mi=0;mi<2;mi++){
      float v0 = acc[mi][j][0]+acc2[mi][j][0];
      float v1 = acc[mi][j][1]+acc2[mi][j][1];
      float v2 = acc[mi][j][2]+acc2[mi][j][2];
      float v3 = acc[mi][j][3]+acc2[mi][j][3];
      float d0 = sqrtf(fmaxf(sqr[mi*2+0] + sqc0 - 2.f*v0, 1e-12f));
      float d1 = sqrtf(fmaxf(sqr[mi*2+0] + sqc1 - 2.f*v1, 1e-12f));
      float d2 = sqrtf(fmaxf(sqr[mi*2+1] + sqc0 - 2.f*v2, 1e-12f));
      float d3 = sqrtf(fmaxf(sqr[mi*2+1] + sqc1 - 2.f*v3, 1e-12f));
      rsum[mi*2+0] += d0 + d1;
      rsum[mi*2+1] += d2 + d3;
      csum[j*2+0]  += d0 + d2;
      csum[j*2+1]  += d1 + d3;
    }
  }

  #pragma unroll
  for (int i=0;i<4;i++){
    rsum[i] += __shfl_xor_sync(0xffffffffu, rsum[i], 1);
    rsum[i] += __shfl_xor_sync(0xffffffffu, rsum[i], 2);
  }
  if ((lane & 3) == 0){
    #pragma unroll
    for (int mi=0;mi<2;mi++)
      #pragma unroll
      for (int h=0;h<2;h++)
        atomicAdd(&g_s[r0 + wm*32 + mi*16 + (lane>>2) + h*8], rsum[mi*2+h]);
  }

  if (!diag){
    #pragma unroll
    for (int i=0;i<8;i++){
      csum[i] += __shfl_xor_sync(0xffffffffu, csum[i], 4);
      csum[i] += __shfl_xor_sync(0xffffffffu, csum[i], 8);
      csum[i] += __shfl_xor_sync(0xffffffffu, csum[i], 16);
    }
    if ((lane >> 2) == 0){
      #pragma unroll
      for (int j=0;j<4;j++){
        int colg = c0 + wn*32 + j*8 + 2*(lane&3);
        atomicAdd(&g_s[colg],   csum[j*2+0]);
        atomicAdd(&g_s[colg+1], csum[j*2+1]);
      }
    }
  }
}

// ---------------------------------------------------------------------------
// k_softmax: per batch softmax over 512 unique scores.
// ---------------------------------------------------------------------------
__global__ void __launch_bounds__(256) k_softmax(
    const int* __restrict__ pairs, float* __restrict__ out)
{
  __shared__ float red[256];
  const int b = blockIdx.x, tid = threadIdx.x;
  const float scale = 1.f/(512.f*0.25f);
  float x0 = g_s[b*HALF + tid      ]*scale;
  float x1 = g_s[b*HALF + 256 + tid]*scale;

  red[tid] = fmaxf(x0,x1);
  __syncthreads();
  for (int o=128;o;o>>=1){ if(tid<o) red[tid]=fmaxf(red[tid],red[tid+o]); __syncthreads(); }
  float mx = red[0];
  __syncthreads();

  float e0 = expf(x0-mx), e1 = expf(x1-mx);
  red[tid] = e0+e1;
  __syncthreads();
  for (int o=128;o;o>>=1){ if(tid<o) red[tid]+=red[tid+o]; __syncthreads(); }
  float inv = 1.f/red[0];

  float w0 = e0*inv, w1 = e1*inv;
  g_w[b*HALF + tid]       = w0;
  g_w[b*HALF + 256 + tid] = w1;

  float* wout = out + NBATCH*EMB;
  {
    int p = b*HALF + tid;
    wout[pairs[2*p]]   = w0*0.5f;
    wout[pairs[2*p+1]] = w0*0.5f;
    p = b*HALF + 256 + tid;
    wout[pairs[2*p]]   = w1*0.5f;
    wout[pairs[2*p+1]] = w1*0.5f;
  }
  if (tid < EMB) out[b*EMB + tid] = 0.f;
}

// ---------------------------------------------------------------------------
// k_fsum: f[b] += sum over a 64-row slice of w[i] * z[i]. grid (8, NBATCH).
// ---------------------------------------------------------------------------
__global__ void __launch_bounds__(256) k_fsum(float* __restrict__ out)
{
  __shared__ float wsh[64];
  __shared__ float red[256*4];
  const int b = blockIdx.y, tid = threadIdx.x;
  const int base = b*HALF + blockIdx.x*64;
  if (tid < 64) wsh[tid] = g_w[base + tid];
  __syncthreads();

  const int c4 = (tid & 31)*4;   // 4-column group
  const int p  = tid >> 5;       // 0..7 row sub-slice (8 rows each)
  float f[4] = {0.f,0.f,0.f,0.f};
  #pragma unroll
  for (int r=0; r<8; r++){
    int ii = p*8 + r;
    float w = wsh[ii];
    size_t gi = (size_t)(base + ii)*EMB + c4;
    uint2 zh = *(const uint2*)(g_zh + gi);
    uint2 zl = *(const uint2*)(g_zl + gi);
    f[0] = fmaf(w, bf_lo(zh.x) + bf_lo(zl.x), f[0]);
    f[1] = fmaf(w, bf_hi(zh.x) + bf_hi(zl.x), f[1]);
    f[2] = fmaf(w, bf_lo(zh.y) + bf_lo(zl.y), f[2]);
    f[3] = fmaf(w, bf_hi(zh.y) + bf_hi(zl.y), f[3]);
  }
  #pragma unroll
  for (int q=0;q<4;q++) red[tid*4+q] = f[q];
  __syncthreads();
  if (tid < 32){
    float a[4] = {0.f,0.f,0.f,0.f};
    #pragma unroll
    for (int pp=0; pp<8; pp++)
      #pragma unroll
      for (int q=0;q<4;q++)
        a[q] += red[(pp*32+tid)*4+q];
    #pragma unroll
    for (int q=0;q<4;q++)
      atomicAdd(&out[b*EMB + tid*4 + q], a[q]);
  }
}

// ---------------------------------------------------------------------------
extern "C" void kernel_launch(void* const* d_in, const int* in_sizes, int n_in,
                              void* d_out, int out_size)
{
  const float* H     = (const float*)d_in[0];
  const int*   pairs = (const int*)  d_in[2];
  const float* W_in  = (const float*)d_in[3];
  const float* b_in  = (const float*)d_in[4];
  const float* Wb    = (const float*)d_in[5];
  const float* bb    = (const float*)d_in[6];
  const float* lng   = (const float*)d_in[7];
  const float* lnb   = (const float*)d_in[8];
  const float* W_out = (const float*)d_in[9];
  const float* b_out = (const float*)d_in[10];
  const float* lnf_g = (const float*)d_in[11];
  const float* lnf_b = (const float*)d_in[12];
  float* out = (float*)d_out;

  // created once on the (uncaptured) correctness call; reused under capture
  static cudaStream_t s2 = nullptr;
  static cudaEvent_t  e1 = nullptr, e2 = nullptr;
  if (!s2){
    cudaStreamCreateWithFlags(&s2, cudaStreamNonBlocking);
    cudaEventCreateWithFlags(&e1, cudaEventDisableTiming);
    cudaEventCreateWithFlags(&e2, cudaEventDisableTiming);
    cudaFuncSetAttribute(k_mega,     cudaFuncAttributeMaxDynamicSharedMemorySize, MEGA_SMEM);
    cudaFuncSetAttribute(k_gram_mma, cudaFuncAttributeMaxDynamicSharedMemorySize, GRM_SMEM);
  }

  const int SPLIT_CTA   = 148;           // mega1 CTAs = one full wave
  const int SPLIT_BATCH = SPLIT_CTA/4;   // 37 batches fully produced by mega1

  k_prep<<<(WT_TOTAL + 255)/256, 256>>>(Wb, W_out, W_in);
  // mega1: batches [0, 37)
  k_mega<<<SPLIT_CTA, 512, MEGA_SMEM>>>(0, H, pairs, b_in, bb, lng, lnb,
                                        b_out, lnf_g, lnf_b);
  cudaEventRecord(e1, 0);
  // mega2: batches [37, 64) — runs while gram1 fills leftover SMs
  k_mega<<<MROWS/128 - SPLIT_CTA, 512, MEGA_SMEM>>>(SPLIT_CTA, H, pairs, b_in,
                                        bb, lng, lnb, b_out, lnf_g, lnf_b);
  // gram1 on side stream, gated on mega1
  cudaStreamWaitEvent(s2, e1, 0);
  k_gram_mma<<<dim3(36, SPLIT_BATCH), 128, GRM_SMEM, s2>>>(0);
  cudaEventRecord(e2, s2);
  // gram2 after mega2 on main stream
  k_gram_mma<<<dim3(36, NBATCH - SPLIT_BATCH), 128, GRM_SMEM>>>(SPLIT_BATCH);
  // join side stream before softmax
  cudaStreamWaitEvent(0, e2, 0);
  k_softmax<<<NBATCH, 256>>>(pairs, out);
  k_fsum<<<dim3(8, NBATCH), 256>>>(out);
}

// round 16
// speedup vs baseline: 1.3369x; 1.0080x over previous
#include <cuda_runtime.h>
#include <cuda_bf16.h>
#include <math.h>
#include <stdint.h>

#define NBATCH 64
#define HALF   512
#define INDIM  64
#define HID    256
#define EMB    128
#define MROWS  (NBATCH*HALF)   // 32768 unique rows
#define LN_EPS 1e-5f

// weight regions inside g_bt_*
#define WOUT_OFS (3*HID*HID)
#define WIN_OFS  (3*HID*HID + EMB*HID)
#define WT_TOTAL (WIN_OFS + HID*INDIM)

// ---------------- device scratch (allocation is forbidden) ------------------
__device__ __align__(16) __nv_bfloat16 g_bt_hi[WT_TOTAL];
__device__ __align__(16) __nv_bfloat16 g_bt_lo[WT_TOTAL];
__device__ __align__(16) __nv_bfloat16 g_zh[MROWS*EMB];   // z hi
__device__ __align__(16) __nv_bfloat16 g_zl[MROWS*EMB];   // z lo
__device__ float g_sq[MROWS];
__device__ float g_s [MROWS];
__device__ float g_w [MROWS];   // normalized softmax weights (unique rows)

// ---------------- helpers ----------------------------------------------------
__device__ __forceinline__ uint32_t smem_u32(const void* p){
  uint32_t a;
  asm("{ .reg .u64 t; cvta.to.shared.u64 t, %1; cvt.u32.u64 %0, t; }" : "=r"(a) : "l"(p));
  return a;
}
__device__ __forceinline__ void cp16(uint32_t dst, const void* src){
  asm volatile("cp.async.cg.shared.global [%0], [%1], 16;\n" :: "r"(dst), "l"(src));
}
#define CP_COMMIT() asm volatile("cp.async.commit_group;\n" ::: "memory")
#define CP_WAIT(n)  asm volatile("cp.async.wait_group %0;\n" :: "n"(n) : "memory")

__device__ __forceinline__ void ldsm4(uint32_t (&r)[4], uint32_t addr){
  asm volatile("ldmatrix.sync.aligned.m8n8.x4.shared.b16 {%0,%1,%2,%3}, [%4];\n"
    : "=r"(r[0]),"=r"(r[1]),"=r"(r[2]),"=r"(r[3]) : "r"(addr));
}
__device__ __forceinline__ void mma16816(float (&d)[4], const uint32_t (&a)[4],
                                         uint32_t b0, uint32_t b1){
  asm volatile("mma.sync.aligned.m16n8k16.row.col.f32.bf16.bf16.f32 "
    "{%0,%1,%2,%3}, {%4,%5,%6,%7}, {%8,%9}, {%0,%1,%2,%3};\n"
    : "+f"(d[0]),"+f"(d[1]),"+f"(d[2]),"+f"(d[3])
    : "r"(a[0]),"r"(a[1]),"r"(a[2]),"r"(a[3]), "r"(b0),"r"(b1));
}
// rows of 64B (32 bf16); 16B column-chunk c in 0..3; XOR swizzle
__device__ __forceinline__ uint32_t swz(int r, int c){
  return (uint32_t)(r*64 + ((c ^ ((r>>1)&3))<<4));
}
__device__ __forceinline__ void split_bf16(float x, __nv_bfloat16& h, __nv_bfloat16& l){
  h = __float2bfloat16(x);
  l = __float2bfloat16(x - __bfloat162float(h));
}
__device__ __forceinline__ void split2(float v0, float v1, uint32_t& whi, uint32_t& wlo){
  __nv_bfloat16 h0,l0,h1,l1;
  split_bf16(v0,h0,l0); split_bf16(v1,h1,l1);
  whi = ((uint32_t)__bfloat16_as_ushort(h1)<<16) | (uint32_t)__bfloat16_as_ushort(h0);
  wlo = ((uint32_t)__bfloat16_as_ushort(l1)<<16) | (uint32_t)__bfloat16_as_ushort(l0);
}
__device__ __forceinline__ float bf_lo(uint32_t w){
  return __bfloat162float(__ushort_as_bfloat16((unsigned short)(w & 0xffffu)));
}
__device__ __forceinline__ float bf_hi(uint32_t w){
  return __bfloat162float(__ushort_as_bfloat16((unsigned short)(w >> 16)));
}

// warp tile 32 rows x 64 cols, one k32 chunk, bf16x3 accumulate
__device__ __forceinline__ void warp_mma_chunk(
    float (&acc)[2][8][4],
    uint32_t aH, uint32_t aL, uint32_t bH, uint32_t bL,
    int wm, int wn, int lane)
{
  #pragma unroll
  for (int kk=0; kk<2; kk++){
    uint32_t ah[2][4], al[2][4];
    #pragma unroll
    for (int mi=0; mi<2; mi++){
      int row = wm*32 + mi*16 + (lane & 15);
      int c   = kk*2 + (lane >> 4);
      uint32_t off = swz(row, c);
      ldsm4(ah[mi], aH + off);
      ldsm4(al[mi], aL + off);
    }
    #pragma unroll
    for (int p=0; p<4; p++){
      int n = wn*64 + p*16 + ((lane>>4)<<3) + (lane & 7);
      int c = kk*2 + ((lane>>3)&1);
      uint32_t off = swz(n, c);
      uint32_t bh[4], bl[4];
      ldsm4(bh, bH + off);
      ldsm4(bl, bL + off);
      #pragma unroll
      for (int mi=0; mi<2; mi++){
        #pragma unroll
        for (int h=0; h<2; h++){
          mma16816(acc[mi][p*2+h], ah[mi], bh[2*h], bh[2*h+1]);
          mma16816(acc[mi][p*2+h], ah[mi], bl[2*h], bl[2*h+1]);
          mma16816(acc[mi][p*2+h], al[mi], bh[2*h], bh[2*h+1]);
        }
      }
    }
  }
}

// warp tile 32 rows x 32 cols, one k32 chunk, bf16x3
__device__ __forceinline__ void warp_mma_chunk32(
    float (&acc)[2][4][4],
    uint32_t aH, uint32_t aL, uint32_t bH, uint32_t bL,
    int wm, int wn, int lane)
{
  #pragma unroll
  for (int kk=0; kk<2; kk++){
    uint32_t ah[2][4], al[2][4];
    #pragma unroll
    for (int mi=0; mi<2; mi++){
      int row = wm*32 + mi*16 + (lane & 15);
      int c   = kk*2 + (lane >> 4);
      uint32_t off = swz(row, c);
      ldsm4(ah[mi], aH + off);
      ldsm4(al[mi], aL + off);
    }
    #pragma unroll
    for (int p=0; p<2; p++){
      int n = wn*32 + p*16 + ((lane>>4)<<3) + (lane & 7);
      int c = kk*2 + ((lane>>3)&1);
      uint32_t off = swz(n, c);
      uint32_t bh[4], bl[4];
      ldsm4(bh, bH + off);
      ldsm4(bl, bL + off);
      #pragma unroll
      for (int mi=0; mi<2; mi++){
        #pragma unroll
        for (int h=0; h<2; h++){
          mma16816(acc[mi][p*2+h], ah[mi], bh[2*h], bh[2*h+1]);
          mma16816(acc[mi][p*2+h], ah[mi], bl[2*h], bl[2*h+1]);
          mma16816(acc[mi][p*2+h], al[mi], bh[2*h], bh[2*h+1]);
        }
      }
    }
  }
}

// gram bf16x3 with dual accumulators
__device__ __forceinline__ void warp_mma_gram3(
    float (&acc)[2][4][4], float (&acc2)[2][4][4],
    uint32_t aH, uint32_t aL, uint32_t bH, uint32_t bL,
    int wm, int wn, int lane)
{
  #pragma unroll
  for (int kk=0; kk<2; kk++){
    uint32_t ah[2][4], al[2][4];
    #pragma unroll
    for (int mi=0; mi<2; mi++){
      int row = wm*32 + mi*16 + (lane & 15);
      int c   = kk*2 + (lane >> 4);
      uint32_t off = swz(row, c);
      ldsm4(ah[mi], aH + off);
      ldsm4(al[mi], aL + off);
    }
    #pragma unroll
    for (int p=0; p<2; p++){
      int n = wn*32 + p*16 + ((lane>>4)<<3) + (lane & 7);
      int c = kk*2 + ((lane>>3)&1);
      uint32_t off = swz(n, c);
      uint32_t bh[4], bl[4];
      ldsm4(bh, bH + off);
      ldsm4(bl, bL + off);
      #pragma unroll
      for (int mi=0; mi<2; mi++){
        #pragma unroll
        for (int h=0; h<2; h++){
          mma16816(acc [mi][p*2+h], ah[mi], bh[2*h], bh[2*h+1]);
          mma16816(acc2[mi][p*2+h], ah[mi], bl[2*h], bl[2*h+1]);
          mma16816(acc2[mi][p*2+h], al[mi], bh[2*h], bh[2*h+1]);
        }
      }
    }
  }
}

// ---------------------------------------------------------------------------
// prep: transpose + hi/lo split of Wb, W_out, W_in; zero g_s
// ---------------------------------------------------------------------------
__global__ void __launch_bounds__(256) k_prep(
    const float* __restrict__ Wb, const float* __restrict__ Wout,
    const float* __restrict__ Win)
{
  int i = blockIdx.x*256 + threadIdx.x;
  if (i < MROWS) g_s[i] = 0.f;
  float v;
  if (i < WOUT_OFS){
    int layer = i >> 16;
    int n  = (i >> 8) & 255;
    int kk = i & 255;
    v = Wb[layer*HID*HID + kk*HID + n];
  } else if (i < WIN_OFS){
    int j = i - WOUT_OFS;
    int n  = j >> 8;
    int kk = j & 255;
    v = Wout[kk*EMB + n];
  } else if (i < WT_TOTAL){
    int j = i - WIN_OFS;
    int n  = j >> 6;
    int kk = j & 63;
    v = Win[kk*HID + n];
  } else return;
  __nv_bfloat16 h, l; split_bf16(v, h, l);
  g_bt_hi[i] = h; g_bt_lo[i] = l;
}

// ---------------------------------------------------------------------------
// k_mega (proven config + cta_base for split launch)
// ---------------------------------------------------------------------------
#define HHI  0
#define HLO  65536
#define BST  131072
#define PRM  196608
#define PART 199680
#define IDX  203776
#define MEGA_SMEM 204800

__global__ void __launch_bounds__(512) k_mega(
    int cta_base,
    const float* __restrict__ H, const int* __restrict__ pairs,
    const float* __restrict__ b_in,
    const float* __restrict__ bb, const float* __restrict__ lng,
    const float* __restrict__ lnb,
    const float* __restrict__ bo, const float* __restrict__ lnf_g,
    const float* __restrict__ lnf_b)
{
  extern __shared__ char smem[];
  const uint32_t sb = smem_u32(smem);
  const int tid = threadIdx.x, lane = tid&31, wid = tid>>5;
  const int wm = wid>>2, wn = wid&3;
  const int row0 = (cta_base + blockIdx.x) * 128;
  int*   li   = (int*)(smem + IDX);
  int*   ri   = li + 128;
  float* prm  = (float*)(smem + PRM);
  float* part = (float*)(smem + PART);

  if (tid < 128){
    li[tid] = pairs[2*(row0+tid)];
    ri[tid] = pairs[2*(row0+tid)+1];
  }
  if (tid < 256) prm[tid] = b_in[tid];
  __syncthreads();

  // ---- delta = |H[li]-H[ri]| into h planes 0,1 (K=64) ----
  #pragma unroll
  for (int u=0; u<2; u++){
    int e = tid + u*512;
    int r = e>>3, g = e&7;
    const float* pl = H + (size_t)li[r]*INDIM + g*8;
    const float* pr = H + (size_t)ri[r]*INDIM + g*8;
    float4 a0 = *(const float4*)pl,     a1 = *(const float4*)(pl+4);
    float4 b0 = *(const float4*)pr,     b1 = *(const float4*)(pr+4);
    float d0=fabsf(a0.x-b0.x), d1=fabsf(a0.y-b0.y), d2=fabsf(a0.z-b0.z), d3=fabsf(a0.w-b0.w);
    float d4=fabsf(a1.x-b1.x), d5=fabsf(a1.y-b1.y), d6=fabsf(a1.z-b1.z), d7=fabsf(a1.w-b1.w);
    uint32_t h0,h1,h2,h3,l0,l1,l2,l3;
    split2(d0,d1,h0,l0); split2(d2,d3,h1,l1);
    split2(d4,d5,h2,l2); split2(d6,d7,h3,l3);
    uint32_t off = (uint32_t)((g>>2)*8192) + swz(r, g&3);
    *(uint4*)(smem + HHI + off) = make_uint4(h0,h1,h2,h3);
    *(uint4*)(smem + HLO + off) = make_uint4(l0,l1,l2,l3);
  }

  auto loadB = [&](const __nv_bfloat16* BH, const __nv_bfloat16* BL,
                   int nrows, int kstride, int c, int s){
    uint32_t base = sb + BST + (uint32_t)s*32768;
    int iters = (nrows*4)/512;
    for (int u=0; u<iters; u++){
      int e = tid + u*512;
      int n = e>>2, q = e&3;
      size_t gi = (size_t)n*kstride + c*32 + q*8;
      uint32_t off = swz(n, q);
      cp16(base + off,         BH + gi);
      cp16(base + 16384 + off, BL + gi);
    }
    CP_COMMIT();
  };

  // ================= layer 0: h = delta @ W_in + b_in =================
  {
    const __nv_bfloat16* BH = g_bt_hi + WIN_OFS;
    const __nv_bfloat16* BL = g_bt_lo + WIN_OFS;
    loadB(BH, BL, 256, INDIM, 0, 0);
    loadB(BH, BL, 256, INDIM, 1, 1);
    float acc[2][8][4];
    #pragma unroll
    for (int mi=0;mi<2;mi++)
      #pragma unroll
      for (int j=0;j<8;j++)
        #pragma unroll
        for (int q=0;q<4;q++) acc[mi][j][q]=0.f;
    CP_WAIT(0);
    __syncthreads();
    warp_mma_chunk(acc, sb+HHI,      sb+HLO,      sb+BST,       sb+BST+16384,       wm, wn, lane);
    warp_mma_chunk(acc, sb+HHI+8192, sb+HLO+8192, sb+BST+32768, sb+BST+32768+16384, wm, wn, lane);
    __syncthreads();

    #pragma unroll
    for (int j=0;j<8;j++){
      int col = wn*64 + j*8 + 2*(lane&3);
      float b0 = prm[col], b1 = prm[col+1];
      int p = wn*2 + (j>>2), qj = j&3;
      #pragma unroll
      for (int mi=0;mi<2;mi++){
        #pragma unroll
        for (int h=0;h<2;h++){
          int rl = wm*32 + mi*16 + (lane>>2) + h*8;
          uint32_t adr = (uint32_t)p*8192 + swz(rl, qj) + 4*(lane&3);
          uint32_t whi, wlo;
          split2(acc[mi][j][h*2]+b0, acc[mi][j][h*2+1]+b1, whi, wlo);
          *(uint32_t*)(smem + HHI + adr) = whi;
          *(uint32_t*)(smem + HLO + adr) = wlo;
        }
      }
    }
    __syncthreads();
  }

  // ================= layers 1..3: h += relu(LN(h @ Wb + bb)) =================
  for (int L=0; L<3; L++){
    const __nv_bfloat16* BH = g_bt_hi + (size_t)L*HID*HID;
    const __nv_bfloat16* BL = g_bt_lo + (size_t)L*HID*HID;
    if (tid < 256){
      prm[tid]     = bb [L*HID+tid];
      prm[256+tid] = lng[L*HID+tid];
      prm[512+tid] = lnb[L*HID+tid];
    }
    loadB(BH, BL, 256, HID, 0, 0);
    loadB(BH, BL, 256, HID, 1, 1);

    float acc[2][8][4];
    #pragma unroll
    for (int mi=0;mi<2;mi++)
      #pragma unroll
      for (int j=0;j<8;j++)
        #pragma unroll
        for (int q=0;q<4;q++) acc[mi][j][q]=0.f;

    for (int c=0;c<8;c++){
      if (c<6) { CP_WAIT(1); } else { CP_WAIT(0); }
      __syncthreads();
      uint32_t bbase = sb + BST + (uint32_t)(c&1)*32768;
      warp_mma_chunk(acc, sb+HHI+(uint32_t)c*8192, sb+HLO+(uint32_t)c*8192,
                     bbase, bbase+16384, wm, wn, lane);
      __syncthreads();
      if (c<6) loadB(BH, BL, 256, HID, c+2, c&1);
    }

    float sum[4]={0.f,0.f,0.f,0.f}, ssq[4]={0.f,0.f,0.f,0.f};
    #pragma unroll
    for (int j=0;j<8;j++){
      int col = wn*64 + j*8 + 2*(lane&3);
      float b0 = prm[col], b1 = prm[col+1];
      #pragma unroll
      for (int mi=0;mi<2;mi++){
        acc[mi][j][0]+=b0; acc[mi][j][1]+=b1; acc[mi][j][2]+=b0; acc[mi][j][3]+=b1;
        sum[mi*2+0] += acc[mi][j][0]+acc[mi][j][1];
        ssq[mi*2+0] += acc[mi][j][0]*acc[mi][j][0]+acc[mi][j][1]*acc[mi][j][1];
        sum[mi*2+1] += acc[mi][j][2]+acc[mi][j][3];
        ssq[mi*2+1] += acc[mi][j][2]*acc[mi][j][2]+acc[mi][j][3]*acc[mi][j][3];
      }
    }
    #pragma unroll
    for (int s=0;s<4;s++){
      sum[s]+=__shfl_xor_sync(0xffffffffu,sum[s],1);
      sum[s]+=__shfl_xor_sync(0xffffffffu,sum[s],2);
      ssq[s]+=__shfl_xor_sync(0xffffffffu,ssq[s],1);
      ssq[s]+=__shfl_xor_sync(0xffffffffu,ssq[s],2);
    }
    if ((lane&3)==0){
      #pragma unroll
      for (int mi=0;mi<2;mi++)
        #pragma unroll
        for (int h=0;h<2;h++){
          int row = wm*32 + mi*16 + (lane>>2) + h*8;
          part[(row*4+wn)*2]   = sum[mi*2+h];
          part[(row*4+wn)*2+1] = ssq[mi*2+h];
        }
    }
    __syncthreads();
    float mu[4], rs[4];
    #pragma unroll
    for (int mi=0;mi<2;mi++)
      #pragma unroll
      for (int h=0;h<2;h++){
        int row = wm*32 + mi*16 + (lane>>2) + h*8;
        float s1 = part[(row*4+0)*2]+part[(row*4+1)*2]+part[(row*4+2)*2]+part[(row*4+3)*2];
        float s2 = part[(row*4+0)*2+1]+part[(row*4+1)*2+1]+part[(row*4+2)*2+1]+part[(row*4+3)*2+1];
        int s = mi*2+h;
        mu[s] = s1*(1.f/256.f);
        float var = s2*(1.f/256.f) - mu[s]*mu[s];
        rs[s] = rsqrtf(fmaxf(var,0.f) + LN_EPS);
      }
    #pragma unroll
    for (int j=0;j<8;j++){
      int col = wn*64 + j*8 + 2*(lane&3);
      float lg0 = prm[256+col], lg1 = prm[256+col+1];
      float lb0 = prm[512+col], lb1 = prm[512+col+1];
      int p = wn*2 + (j>>2), qj = j&3;
      #pragma unroll
      for (int mi=0;mi<2;mi++){
        #pragma unroll
        for (int h=0;h<2;h++){
          int rl = wm*32 + mi*16 + (lane>>2) + h*8;
          int s = mi*2+h;
          uint32_t adr = (uint32_t)p*8192 + swz(rl, qj) + 4*(lane&3);
          uint32_t ohh = *(uint32_t*)(smem + HHI + adr);
          uint32_t oll = *(uint32_t*)(smem + HLO + adr);
          float old0 = bf_lo(ohh) + bf_lo(oll);
          float old1 = bf_hi(ohh) + bf_hi(oll);
          float t0 = fmaxf((acc[mi][j][h*2]  -mu[s])*rs[s]*lg0 + lb0, 0.f);
          float t1 = fmaxf((acc[mi][j][h*2+1]-mu[s])*rs[s]*lg1 + lb1, 0.f);
          uint32_t whi, wlo;
          split2(old0+t0, old1+t1, whi, wlo);
          *(uint32_t*)(smem + HHI + adr) = whi;
          *(uint32_t*)(smem + HLO + adr) = wlo;
        }
      }
    }
    __syncthreads();
  }

  // ================= out layer: z = LN(h @ W_out + b_out), sq =================
  {
    const __nv_bfloat16* BH = g_bt_hi + WOUT_OFS;
    const __nv_bfloat16* BL = g_bt_lo + WOUT_OFS;
    if (tid < 128){
      prm[tid]     = bo[tid];
      prm[256+tid] = lnf_g[tid];
      prm[512+tid] = lnf_b[tid];
    }
    loadB(BH, BL, 128, HID, 0, 0);
    loadB(BH, BL, 128, HID, 1, 1);

    float acc[2][4][4];
    #pragma unroll
    for (int mi=0;mi<2;mi++)
      #pragma unroll
      for (int j=0;j<4;j++)
        #pragma unroll
        for (int q=0;q<4;q++) acc[mi][j][q]=0.f;

    for (int c=0;c<8;c++){
      if (c<6) { CP_WAIT(1); } else { CP_WAIT(0); }
      __syncthreads();
      uint32_t bbase = sb + BST + (uint32_t)(c&1)*32768;
      warp_mma_chunk32(acc, sb+HHI+(uint32_t)c*8192, sb+HLO+(uint32_t)c*8192,
                       bbase, bbase+16384, wm, wn, lane);
      __syncthreads();
      if (c<6) loadB(BH, BL, 128, HID, c+2, c&1);
    }

    float sum[4]={0.f,0.f,0.f,0.f}, ssq[4]={0.f,0.f,0.f,0.f};
    #pragma unroll
    for (int j=0;j<4;j++){
      int col = wn*32 + j*8 + 2*(lane&3);
      float b0 = prm[col], b1 = prm[col+1];
      #pragma unroll
      for (int mi=0;mi<2;mi++){
        acc[mi][j][0]+=b0; acc[mi][j][1]+=b1; acc[mi][j][2]+=b0; acc[mi][j][3]+=b1;
        sum[mi*2+0] += acc[mi][j][0]+acc[mi][j][1];
        ssq[mi*2+0] += acc[mi][j][0]*acc[mi][j][0]+acc[mi][j][1]*acc[mi][j][1];
        sum[mi*2+1] += acc[mi][j][2]+acc[mi][j][3];
        ssq[mi*2+1] += acc[mi][j][2]*acc[mi][j][2]+acc[mi][j][3]*acc[mi][j][3];
      }
    }
    #pragma unroll
    for (int s=0;s<4;s++){
      sum[s]+=__shfl_xor_sync(0xffffffffu,sum[s],1);
      sum[s]+=__shfl_xor_sync(0xffffffffu,sum[s],2);
      ssq[s]+=__shfl_xor_sync(0xffffffffu,ssq[s],1);
      ssq[s]+=__shfl_xor_sync(0xffffffffu,ssq[s],2);
    }
    if ((lane&3)==0){
      #pragma unroll
      for (int mi=0;mi<2;mi++)
        #pragma unroll
        for (int h=0;h<2;h++){
          int row = wm*32 + mi*16 + (lane>>2) + h*8;
          part[(row*4+wn)*2]   = sum[mi*2+h];
          part[(row*4+wn)*2+1] = ssq[mi*2+h];
        }
    }
    __syncthreads();
    float mu[4], rs[4];
    #pragma unroll
    for (int mi=0;mi<2;mi++)
      #pragma unroll
      for (int h=0;h<2;h++){
        int row = wm*32 + mi*16 + (lane>>2) + h*8;
        float s1 = part[(row*4+0)*2]+part[(row*4+1)*2]+part[(row*4+2)*2]+part[(row*4+3)*2];
        float s2 = part[(row*4+0)*2+1]+part[(row*4+1)*2+1]+part[(row*4+2)*2+1]+part[(row*4+3)*2+1];
        int s = mi*2+h;
        mu[s] = s1*(1.f/128.f);
        float var = s2*(1.f/128.f) - mu[s]*mu[s];
        rs[s] = rsqrtf(fmaxf(var,0.f) + LN_EPS);
      }
    float qs[4]={0.f,0.f,0.f,0.f};
    #pragma unroll
    for (int j=0;j<4;j++){
      int col = wn*32 + j*8 + 2*(lane&3);
      float lg0 = prm[256+col], lg1 = prm[256+col+1];
      float lb0 = prm[512+col], lb1 = prm[512+col+1];
      #pragma unroll
      for (int mi=0;mi<2;mi++){
        #pragma unroll
        for (int h=0;h<2;h++){
          int rl = wm*32 + mi*16 + (lane>>2) + h*8;
          int s = mi*2+h;
          float t0 = (acc[mi][j][h*2]  -mu[s])*rs[s]*lg0 + lb0;
          float t1 = (acc[mi][j][h*2+1]-mu[s])*rs[s]*lg1 + lb1;
          qs[s] += t0*t0 + t1*t1;
          uint32_t whi, wlo;
          split2(t0, t1, whi, wlo);
          size_t gi = (size_t)(row0+rl)*EMB + col;
          *(uint32_t*)(g_zh + gi) = whi;
          *(uint32_t*)(g_zl + gi) = wlo;
        }
      }
    }
    __syncthreads();
    #pragma unroll
    for (int s=0;s<4;s++){
      qs[s]+=__shfl_xor_sync(0xffffffffu,qs[s],1);
      qs[s]+=__shfl_xor_sync(0xffffffffu,qs[s],2);
    }
    if ((lane&3)==0){
      #pragma unroll
      for (int mi=0;mi<2;mi++)
        #pragma unroll
        for (int h=0;h<2;h++){
          int row = wm*32 + mi*16 + (lane>>2) + h*8;
          part[row*4+wn] = qs[mi*2+h];
        }
    }
    __syncthreads();
    if (wn==0 && (lane&3)==0){
      #pragma unroll
      for (int mi=0;mi<2;mi++)
        #pragma unroll
        for (int h=0;h<2;h++){
          int row = wm*32 + mi*16 + (lane>>2) + h*8;
          g_sq[row0+row] = part[row*4+0]+part[row*4+1]+part[row*4+2]+part[row*4+3];
        }
    }
  }
}

// ---------------------------------------------------------------------------
// k_gram_mma: bf16x3 with dual accumulators; batch_base for split launch.
// ---------------------------------------------------------------------------
#define GRM_SMEM 65536
__global__ void __launch_bounds__(128) k_gram_mma(int batch_base)
{
  extern __shared__ char smem[];
  const uint32_t sb = smem_u32(smem);
  const int tid = threadIdx.x, lane = tid&31, wid = tid>>5;
  const int wm = wid>>1, wn = wid&1;

  int t = blockIdx.x, rt = 0;
  while (t >= 8 - rt){ t -= 8 - rt; rt++; }
  const int ct = rt + t;
  const bool diag = (rt == ct);
  const int bofs = (batch_base + blockIdx.y) * HALF;
  const int r0 = bofs + rt*64;
  const int c0 = bofs + ct*64;

  #pragma unroll
  for (int u=0; u<8; u++){
    int e = tid + u*128;
    int r = e>>4, tt = e&15;
    int c = tt>>2, q = tt&3;
    uint32_t off = (uint32_t)(c*4096) + swz(r, q);
    size_t gi = (size_t)(r0+r)*EMB + c*32 + q*8;
    cp16(sb + off,         g_zh + gi);
    cp16(sb + 16384 + off, g_zl + gi);
  }
  if (!diag){
    #pragma unroll
    for (int u=0; u<8; u++){
      int e = tid + u*128;
      int r = e>>4, tt = e&15;
      int c = tt>>2, q = tt&3;
      uint32_t off = (uint32_t)(c*4096) + swz(r, q);
      size_t gi = (size_t)(c0+r)*EMB + c*32 + q*8;
      cp16(sb + 32768 + off, g_zh + gi);
      cp16(sb + 49152 + off, g_zl + gi);
    }
  }
  CP_COMMIT(); CP_WAIT(0);
  __syncthreads();

  const uint32_t bHb = diag ? sb : (sb + 32768);
  const uint32_t bLb = diag ? (sb + 16384) : (sb + 49152);

  float acc[2][4][4], acc2[2][4][4];
  #pragma unroll
  for (int mi=0;mi<2;mi++)
    #pragma unroll
    for (int j=0;j<4;j++)
      #pragma unroll
      for (int q=0;q<4;q++){ acc[mi][j][q]=0.f; acc2[mi][j][q]=0.f; }

  #pragma unroll
  for (int c=0;c<4;c++)
    warp_mma_gram3(acc, acc2, sb + c*4096, sb + 16384 + c*4096,
                   bHb + c*4096, bLb + c*4096, wm, wn, lane);

  float sqr[4];
  #pragma unroll
  for (int mi=0;mi<2;mi++)
    #pragma unroll
    for (int h=0;h<2;h++)
      sqr[mi*2+h] = g_sq[r0 + wm*32 + mi*16 + (lane>>2) + h*8];

  float rsum[4] = {0.f,0.f,0.f,0.f};
  float csum[8] = {0.f,0.f,0.f,0.f,0.f,0.f,0.f,0.f};
  #pragma unroll
  for (int j=0;j<4;j++){
    int colg = c0 + wn*32 + j*8 + 2*(lane&3);
    float sqc0 = g_sq[colg], sqc1 = g_sq[colg+1];
    #pragma unroll
    for (int mi=0;mi<2;mi++){
      float v0 = acc[mi][j][0]+acc2[mi][j][0];
      float v1 = acc[mi][j][1]+acc2[mi][j][1];
      float v2 = acc[mi][j][2]+acc2[mi][j][2];
      float v3 = acc[mi][j][3]+acc2[mi][j][3];
      float d0 = sqrtf(fmaxf(sqr[mi*2+0] + sqc0 - 2.f*v0, 1e-12f));
      float d1 = sqrtf(fmaxf(sqr[mi*2+0] + sqc1 - 2.f*v1, 1e-12f));
      float d2 = sqrtf(fmaxf(sqr[mi*2+1] + sqc0 - 2.f*v2, 1e-12f));
      float d3 = sqrtf(fmaxf(sqr[mi*2+1] + sqc1 - 2.f*v3, 1e-12f));
      rsum[mi*2+0] += d0 + d1;
      rsum[mi*2+1] += d2 + d3;
      csum[j*2+0]  += d0 + d2;
      csum[j*2+1]  += d1 + d3;
    }
  }

  #pragma unroll
  for (int i=0;i<4;i++){
    rsum[i] += __shfl_xor_sync(0xffffffffu, rsum[i], 1);
    rsum[i] += __shfl_xor_sync(0xffffffffu, rsum[i], 2);
  }
  if ((lane & 3) == 0){
    #pragma unroll
    for (int mi=0;mi<2;mi++)
      #pragma unroll
      for (int h=0;h<2;h++)
        atomicAdd(&g_s[r0 + wm*32 + mi*16 + (lane>>2) + h*8], rsum[mi*2+h]);
  }

  if (!diag){
    #pragma unroll
    for (int i=0;i<8;i++){
      csum[i] += __shfl_xor_sync(0xffffffffu, csum[i], 4);
      csum[i] += __shfl_xor_sync(0xffffffffu, csum[i], 8);
      csum[i] += __shfl_xor_sync(0xffffffffu, csum[i], 16);
    }
    if ((lane >> 2) == 0){
      #pragma unroll
      for (int j=0;j<4;j++){
        int colg = c0 + wn*32 + j*8 + 2*(lane&3);
        atomicAdd(&g_s[colg],   csum[j*2+0]);
        atomicAdd(&g_s[colg+1], csum[j*2+1]);
      }
    }
  }
}

// ---------------------------------------------------------------------------
// k_softmax: per batch softmax over 512 unique scores.
// ---------------------------------------------------------------------------
__global__ void __launch_bounds__(256) k_softmax(
    const int* __restrict__ pairs, float* __restrict__ out)
{
  __shared__ float red[256];
  const int b = blockIdx.x, tid = threadIdx.x;
  const float scale = 1.f/(512.f*0.25f);
  float x0 = g_s[b*HALF + tid      ]*scale;
  float x1 = g_s[b*HALF + 256 + tid]*scale;

  red[tid] = fmaxf(x0,x1);
  __syncthreads();
  for (int o=128;o;o>>=1){ if(tid<o) red[tid]=fmaxf(red[tid],red[tid+o]); __syncthreads(); }
  float mx = red[0];
  __syncthreads();

  float e0 = expf(x0-mx), e1 = expf(x1-mx);
  red[tid] = e0+e1;
  __syncthreads();
  for (int o=128;o;o>>=1){ if(tid<o) red[tid]+=red[tid+o]; __syncthreads(); }
  float inv = 1.f/red[0];

  float w0 = e0*inv, w1 = e1*inv;
  g_w[b*HALF + tid]       = w0;
  g_w[b*HALF + 256 + tid] = w1;

  float* wout = out + NBATCH*EMB;
  {
    int p = b*HALF + tid;
    wout[pairs[2*p]]   = w0*0.5f;
    wout[pairs[2*p+1]] = w0*0.5f;
    p = b*HALF + 256 + tid;
    wout[pairs[2*p]]   = w1*0.5f;
    wout[pairs[2*p+1]] = w1*0.5f;
  }
  if (tid < EMB) out[b*EMB + tid] = 0.f;
}

// ---------------------------------------------------------------------------
// k_fsum: f[b] += sum over a 64-row slice of w[i] * z[i]. grid (8, NBATCH).
// ---------------------------------------------------------------------------
__global__ void __launch_bounds__(256) k_fsum(float* __restrict__ out)
{
  __shared__ float wsh[64];
  __shared__ float red[256*4];
  const int b = blockIdx.y, tid = threadIdx.x;
  const int base = b*HALF + blockIdx.x*64;
  if (tid < 64) wsh[tid] = g_w[base + tid];
  __syncthreads();

  const int c4 = (tid & 31)*4;   // 4-column group
  const int p  = tid >> 5;       // 0..7 row sub-slice (8 rows each)
  float f[4] = {0.f,0.f,0.f,0.f};
  #pragma unroll
  for (int r=0; r<8; r++){
    int ii = p*8 + r;
    float w = wsh[ii];
    size_t gi = (size_t)(base + ii)*EMB + c4;
    uint2 zh = *(const uint2*)(g_zh + gi);
    uint2 zl = *(const uint2*)(g_zl + gi);
    f[0] = fmaf(w, bf_lo(zh.x) + bf_lo(zl.x), f[0]);
    f[1] = fmaf(w, bf_hi(zh.x) + bf_hi(zl.x), f[1]);
    f[2] = fmaf(w, bf_lo(zh.y) + bf_lo(zl.y), f[2]);
    f[3] = fmaf(w, bf_hi(zh.y) + bf_hi(zl.y), f[3]);
  }
  #pragma unroll
  for (int q=0;q<4;q++) red[tid*4+q] = f[q];
  __syncthreads();
  if (tid < 32){
    float a[4] = {0.f,0.f,0.f,0.f};
    #pragma unroll
    for (int pp=0; pp<8; pp++)
      #pragma unroll
      for (int q=0;q<4;q++)
        a[q] += red[(pp*32+tid)*4+q];
    #pragma unroll
    for (int q=0;q<4;q++)
      atomicAdd(&out[b*EMB + tid*4 + q], a[q]);
  }
}

// ---------------------------------------------------------------------------
extern "C" void kernel_launch(void* const* d_in, const int* in_sizes, int n_in,
                              void* d_out, int out_size)
{
  const float* H     = (const float*)d_in[0];
  const int*   pairs = (const int*)  d_in[2];
  const float* W_in  = (const float*)d_in[3];
  const float* b_in  = (const float*)d_in[4];
  const float* Wb    = (const float*)d_in[5];
  const float* bb    = (const float*)d_in[6];
  const float* lng   = (const float*)d_in[7];
  const float* lnb   = (const float*)d_in[8];
  const float* W_out = (const float*)d_in[9];
  const float* b_out = (const float*)d_in[10];
  const float* lnf_g = (const float*)d_in[11];
  const float* lnf_b = (const float*)d_in[12];
  float* out = (float*)d_out;

  // created once on the (uncaptured) correctness call; reused under capture
  static cudaStream_t s2 = nullptr, s3 = nullptr;
  static cudaEvent_t  e1 = nullptr, e2 = nullptr, e3 = nullptr, e4 = nullptr;
  if (!s2){
    cudaStreamCreateWithFlags(&s2, cudaStreamNonBlocking);
    cudaStreamCreateWithFlags(&s3, cudaStreamNonBlocking);
    cudaEventCreateWithFlags(&e1, cudaEventDisableTiming);
    cudaEventCreateWithFlags(&e2, cudaEventDisableTiming);
    cudaEventCreateWithFlags(&e3, cudaEventDisableTiming);
    cudaEventCreateWithFlags(&e4, cudaEventDisableTiming);
    cudaFuncSetAttribute(k_mega,     cudaFuncAttributeMaxDynamicSharedMemorySize, MEGA_SMEM);
    cudaFuncSetAttribute(k_gram_mma, cudaFuncAttributeMaxDynamicSharedMemorySize, GRM_SMEM);
  }

  const int S1_CTA = 148;            // mega1: batches [0,37)
  const int S1_B   = 37;
  const int S2_CTA = 56;             // mega2a: batches [37,51)
  const int S2_B   = 14;
  const int S3_CTA = 256 - S1_CTA - S2_CTA;   // 52: batches [51,64)
  const int S3_B   = NBATCH - S1_B - S2_B;    // 13

  k_prep<<<(WT_TOTAL + 255)/256, 256>>>(Wb, W_out, W_in);
  // mega1 (wave 1): batches [0, 37)
  k_mega<<<S1_CTA, 512, MEGA_SMEM>>>(0, H, pairs, b_in, bb, lng, lnb,
                                     b_out, lnf_g, lnf_b);
  cudaEventRecord(e1, 0);
  // mega2a (wave 2, main): batches [37, 51)
  k_mega<<<S2_CTA, 512, MEGA_SMEM>>>(S1_CTA, H, pairs, b_in, bb, lng, lnb,
                                     b_out, lnf_g, lnf_b);
  cudaEventRecord(e3, 0);
  // mega2b (wave 2, s3, concurrent with mega2a): batches [51, 64)
  cudaStreamWaitEvent(s3, e1, 0);
  k_mega<<<S3_CTA, 512, MEGA_SMEM, s3>>>(S1_CTA + S2_CTA, H, pairs, b_in,
                                     bb, lng, lnb, b_out, lnf_g, lnf_b);
  cudaEventRecord(e4, s3);
  // gram chain on s2: batches [0,37) after mega1, then [37,51) after mega2a
  cudaStreamWaitEvent(s2, e1, 0);
  k_gram_mma<<<dim3(36, S1_B), 128, GRM_SMEM, s2>>>(0);
  cudaStreamWaitEvent(s2, e3, 0);
  k_gram_mma<<<dim3(36, S2_B), 128, GRM_SMEM, s2>>>(S1_B);
  cudaEventRecord(e2, s2);
  // main: gram for [51,64) after mega2b, then join and finish
  cudaStreamWaitEvent(0, e4, 0);
  k_gram_mma<<<dim3(36, S3_B), 128, GRM_SMEM>>>(S1_B + S2_B);
  cudaStreamWaitEvent(0, e2, 0);
  k_softmax<<<NBATCH, 256>>>(pairs, out);
  k_fsum<<<dim3(8, NBATCH), 256>>>(out);
}